// round 1
// baseline (speedup 1.0000x reference)
#include <cuda_runtime.h>
#include <math.h>

#define SEQ    2048
#define DMODEL 5120
#define NHEAD  40
#define HDIM   128
#define NQKV   15360
#define ATT_SCALE 0.08838834764831845f   // 128^-0.5

// Scratch (device globals — no allocation allowed)
__device__ float g_qkv[(size_t)SEQ * NQKV];   // QKV projection output [S, 3*DIM]
__device__ float g_q[(size_t)SEQ * DMODEL];   // normalized+roped Q, layout [H, S, D]
__device__ float g_k[(size_t)SEQ * DMODEL];   // normalized+roped K, layout [H, S, D]
__device__ float g_ctx[(size_t)SEQ * DMODEL]; // attention output  [S, DIM]

// ---------------------------------------------------------------------------
// GEMM: C[M,N] = A[M,K] @ B[K,N] + bias[N]
// 128x128 block tile, BK=8, 256 threads, 8x8 per-thread (2x2 groups of 4x4).
// ---------------------------------------------------------------------------
__global__ __launch_bounds__(256) void sgemm_bias(
    const float* __restrict__ A, const float* __restrict__ B,
    const float* __restrict__ bias, float* __restrict__ C,
    int M, int N, int K)
{
    __shared__ float As[8 * 128];   // [k][m]
    __shared__ float Bs[8 * 128];   // [k][n]

    const int tid = threadIdx.x;
    const int tx = tid & 15;        // col group
    const int ty = tid >> 4;        // row group

    const float* Ab = A + (size_t)blockIdx.y * 128 * K;
    const float* Bb = B + (size_t)blockIdx.x * 128;

    const int arow = tid >> 1;            // 0..127
    const int acol = (tid & 1) * 4;       // 0 or 4
    const int brow = tid >> 5;            // 0..7
    const int bcol = (tid & 31) * 4;      // 0..124

    float acc[8][8];
#pragma unroll
    for (int i = 0; i < 8; i++)
#pragma unroll
        for (int j = 0; j < 8; j++) acc[i][j] = 0.0f;

    for (int k0 = 0; k0 < K; k0 += 8) {
        float4 av = *(const float4*)(Ab + (size_t)arow * K + k0 + acol);
        As[(acol + 0) * 128 + arow] = av.x;
        As[(acol + 1) * 128 + arow] = av.y;
        As[(acol + 2) * 128 + arow] = av.z;
        As[(acol + 3) * 128 + arow] = av.w;
        *(float4*)(Bs + brow * 128 + bcol) =
            *(const float4*)(Bb + (size_t)(k0 + brow) * N + bcol);
        __syncthreads();

#pragma unroll
        for (int kk = 0; kk < 8; kk++) {
            float4 a0 = *(float4*)(As + kk * 128 + ty * 4);
            float4 a1 = *(float4*)(As + kk * 128 + 64 + ty * 4);
            float4 b0 = *(float4*)(Bs + kk * 128 + tx * 4);
            float4 b1 = *(float4*)(Bs + kk * 128 + 64 + tx * 4);
            float a[8] = {a0.x, a0.y, a0.z, a0.w, a1.x, a1.y, a1.z, a1.w};
            float b[8] = {b0.x, b0.y, b0.z, b0.w, b1.x, b1.y, b1.z, b1.w};
#pragma unroll
            for (int i = 0; i < 8; i++)
#pragma unroll
                for (int j = 0; j < 8; j++)
                    acc[i][j] = fmaf(a[i], b[j], acc[i][j]);
        }
        __syncthreads();
    }

#pragma unroll
    for (int ii = 0; ii < 2; ii++)
#pragma unroll
        for (int i = 0; i < 4; i++) {
            int r = blockIdx.y * 128 + ii * 64 + ty * 4 + i;
#pragma unroll
            for (int jj = 0; jj < 2; jj++)
#pragma unroll
                for (int j = 0; j < 4; j++) {
                    int c = blockIdx.x * 128 + jj * 64 + tx * 4 + j;
                    C[(size_t)r * N + c] = acc[ii * 4 + i][jj * 4 + j] + bias[c];
                }
        }
}

// ---------------------------------------------------------------------------
// Fused RMSNorm (over full 5120) + RoPE for Q and K. One block per token.
// Writes Q,K head-major: [H, S, D].
// ---------------------------------------------------------------------------
__global__ __launch_bounds__(256) void norm_rope(
    const float* __restrict__ cosp, const float* __restrict__ sinp,
    const float* __restrict__ wq, const float* __restrict__ wk)
{
    const int s = blockIdx.x;
    const int tid = threadIdx.x;
    const float* qrow = g_qkv + (size_t)s * NQKV;
    const float* krow = qrow + DMODEL;

    float sq = 0.f, sk = 0.f;
    for (int i = tid; i < DMODEL; i += 256) {
        float a = qrow[i]; sq += a * a;
        float b = krow[i]; sk += b * b;
    }
#pragma unroll
    for (int off = 16; off; off >>= 1) {
        sq += __shfl_xor_sync(0xffffffffu, sq, off);
        sk += __shfl_xor_sync(0xffffffffu, sk, off);
    }
    __shared__ float shq[8], shk[8];
    if ((tid & 31) == 0) { shq[tid >> 5] = sq; shk[tid >> 5] = sk; }
    __syncthreads();
    float tq = 0.f, tk = 0.f;
#pragma unroll
    for (int i = 0; i < 8; i++) { tq += shq[i]; tk += shk[i]; }
    const float rq = rsqrtf(tq / DMODEL + 1e-6f);
    const float rk = rsqrtf(tk / DMODEL + 1e-6f);

    for (int p = tid; p < DMODEL / 2; p += 256) {
        const int i0 = 2 * p;
        const int h = i0 >> 7;          // head
        const int dl = i0 & 127;        // d within head (even)
        const float c  = cosp[s * HDIM + dl];
        const float sn = sinp[s * HDIM + dl];
        float q0 = qrow[i0] * rq * wq[i0];
        float q1 = qrow[i0 + 1] * rq * wq[i0 + 1];
        float k0 = krow[i0] * rk * wk[i0];
        float k1 = krow[i0 + 1] * rk * wk[i0 + 1];
        const size_t o = (size_t)h * SEQ * HDIM + (size_t)s * HDIM + dl;
        g_q[o]     = q0 * c - q1 * sn;
        g_q[o + 1] = q0 * sn + q1 * c;
        g_k[o]     = k0 * c - k1 * sn;
        g_k[o + 1] = k0 * sn + k1 * c;
    }
}

// ---------------------------------------------------------------------------
// Flash-style attention, fp32. Block = (q-tile of 64 rows, one head).
// K processed in tiles of 64 with online softmax. V read from g_qkv in place.
// smem: Qs[128][64] Ks[128][64] Vs[64][128] Ps[64][64]  = 114688 bytes.
// ---------------------------------------------------------------------------
__global__ __launch_bounds__(256) void flash_attn(float* __restrict__ ctx)
{
    extern __shared__ float sm[];
    float* Qs = sm;            // d-major [128][64]
    float* Ks = sm + 8192;     // d-major [128][64]
    float* Vs = sm + 16384;    // key-major [64][128]
    float* Ps = sm + 24576;    // [64][64]

    const int qt = blockIdx.x;
    const int h  = blockIdx.y;
    const int tid = threadIdx.x;
    const int tx = tid & 15;
    const int ty = tid >> 4;
    const int q0 = qt * 64;

    const float* Qh = g_q + (size_t)h * SEQ * HDIM;
    const float* Kh = g_k + (size_t)h * SEQ * HDIM;
    const float* Vg = g_qkv + 2 * DMODEL + h * HDIM;   // + s*NQKV + d

    // load Q tile transposed
    for (int l = tid; l < 64 * 32; l += 256) {
        int r = l >> 5, c4 = (l & 31) * 4;
        float4 v = *(const float4*)(Qh + (size_t)(q0 + r) * HDIM + c4);
        Qs[(c4 + 0) * 64 + r] = v.x;
        Qs[(c4 + 1) * 64 + r] = v.y;
        Qs[(c4 + 2) * 64 + r] = v.z;
        Qs[(c4 + 3) * 64 + r] = v.w;
    }

    float o[4][8];
#pragma unroll
    for (int i = 0; i < 4; i++)
#pragma unroll
        for (int j = 0; j < 8; j++) o[i][j] = 0.f;
    float m[4] = {-1e30f, -1e30f, -1e30f, -1e30f};
    float lsum[4] = {0.f, 0.f, 0.f, 0.f};

    for (int kt = 0; kt < SEQ / 64; kt++) {
        __syncthreads();   // prior iter's reads of Ks/Vs/Ps done
        // load K tile transposed, V tile row-major
        for (int l = tid; l < 64 * 32; l += 256) {
            int r = l >> 5, c4 = (l & 31) * 4;
            float4 v = *(const float4*)(Kh + (size_t)(kt * 64 + r) * HDIM + c4);
            Ks[(c4 + 0) * 64 + r] = v.x;
            Ks[(c4 + 1) * 64 + r] = v.y;
            Ks[(c4 + 2) * 64 + r] = v.z;
            Ks[(c4 + 3) * 64 + r] = v.w;
            float4 w = *(const float4*)(Vg + (size_t)(kt * 64 + r) * NQKV + c4);
            *(float4*)(Vs + r * 128 + c4) = w;
        }
        __syncthreads();

        // scores: 64x64 over d=128
        float sc[4][4];
#pragma unroll
        for (int i = 0; i < 4; i++)
#pragma unroll
            for (int j = 0; j < 4; j++) sc[i][j] = 0.f;
        for (int kk = 0; kk < HDIM; kk++) {
            float4 qa = *(float4*)(Qs + kk * 64 + ty * 4);
            float4 kb = *(float4*)(Ks + kk * 64 + tx * 4);
            float a[4] = {qa.x, qa.y, qa.z, qa.w};
            float b[4] = {kb.x, kb.y, kb.z, kb.w};
#pragma unroll
            for (int i = 0; i < 4; i++)
#pragma unroll
                for (int j = 0; j < 4; j++)
                    sc[i][j] = fmaf(a[i], b[j], sc[i][j]);
        }

        // online softmax per row (rows owned across 16-lane groups)
#pragma unroll
        for (int i = 0; i < 4; i++) {
            float mx = -1e30f;
#pragma unroll
            for (int j = 0; j < 4; j++) {
                sc[i][j] *= ATT_SCALE;
                mx = fmaxf(mx, sc[i][j]);
            }
#pragma unroll
            for (int off = 8; off; off >>= 1)
                mx = fmaxf(mx, __shfl_xor_sync(0xffffffffu, mx, off, 16));
            float mnew = fmaxf(m[i], mx);
            float fs = __expf(m[i] - mnew);
            float ps[4], psum = 0.f;
#pragma unroll
            for (int j = 0; j < 4; j++) {
                ps[j] = __expf(sc[i][j] - mnew);
                psum += ps[j];
            }
#pragma unroll
            for (int off = 8; off; off >>= 1)
                psum += __shfl_xor_sync(0xffffffffu, psum, off, 16);
            lsum[i] = lsum[i] * fs + psum;
            m[i] = mnew;
#pragma unroll
            for (int c = 0; c < 8; c++) o[i][c] *= fs;
#pragma unroll
            for (int j = 0; j < 4; j++)
                Ps[(ty * 4 + i) * 64 + tx * 4 + j] = ps[j];
        }
        __syncthreads();

        // O += P @ V  (rows ty*4.., cols {tx*4.., 64+tx*4..})
        for (int kk = 0; kk < 64; kk++) {
            float4 v0 = *(float4*)(Vs + kk * 128 + tx * 4);
            float4 v1 = *(float4*)(Vs + kk * 128 + 64 + tx * 4);
#pragma unroll
            for (int i = 0; i < 4; i++) {
                float p = Ps[(ty * 4 + i) * 64 + kk];
                o[i][0] = fmaf(p, v0.x, o[i][0]);
                o[i][1] = fmaf(p, v0.y, o[i][1]);
                o[i][2] = fmaf(p, v0.z, o[i][2]);
                o[i][3] = fmaf(p, v0.w, o[i][3]);
                o[i][4] = fmaf(p, v1.x, o[i][4]);
                o[i][5] = fmaf(p, v1.y, o[i][5]);
                o[i][6] = fmaf(p, v1.z, o[i][6]);
                o[i][7] = fmaf(p, v1.w, o[i][7]);
            }
        }
    }

#pragma unroll
    for (int i = 0; i < 4; i++) {
        float inv = 1.0f / lsum[i];
        int r = q0 + ty * 4 + i;
        size_t base = (size_t)r * DMODEL + h * HDIM;
#pragma unroll
        for (int j = 0; j < 4; j++) {
            ctx[base + tx * 4 + j]      = o[i][j] * inv;
            ctx[base + 64 + tx * 4 + j] = o[i][4 + j] * inv;
        }
    }
}

// ---------------------------------------------------------------------------
extern "C" void kernel_launch(void* const* d_in, const int* in_sizes, int n_in,
                              void* d_out, int out_size)
{
    const float* x     = (const float*)d_in[0];
    const float* cosp  = (const float*)d_in[1];
    const float* sinp  = (const float*)d_in[2];
    const float* w_qkv = (const float*)d_in[3];
    const float* b_qkv = (const float*)d_in[4];
    const float* wq    = (const float*)d_in[5];
    const float* wk    = (const float*)d_in[6];
    const float* w_out = (const float*)d_in[7];
    const float* b_out = (const float*)d_in[8];
    float* out = (float*)d_out;

    float *qkv_p, *ctx_p;
    cudaGetSymbolAddress((void**)&qkv_p, g_qkv);
    cudaGetSymbolAddress((void**)&ctx_p, g_ctx);

    // 1) QKV projection: [2048,5120] @ [5120,15360] + b
    sgemm_bias<<<dim3(NQKV / 128, SEQ / 128), 256>>>(
        x, w_qkv, b_qkv, qkv_p, SEQ, NQKV, DMODEL);

    // 2) RMSNorm + RoPE -> head-major Q,K
    norm_rope<<<SEQ, 256>>>(cosp, sinp, wq, wk);

    // 3) attention
    cudaFuncSetAttribute(flash_attn, cudaFuncAttributeMaxDynamicSharedMemorySize,
                         114688);
    flash_attn<<<dim3(SEQ / 64, NHEAD), 256, 114688>>>(ctx_p);

    // 4) output projection: [2048,5120] @ [5120,5120] + b
    sgemm_bias<<<dim3(DMODEL / 128, SEQ / 128), 256>>>(
        ctx_p, w_out, b_out, out, SEQ, DMODEL, DMODEL);
}

// round 5
// speedup vs baseline: 2.2388x; 2.2388x over previous
#include <cuda_runtime.h>
#include <cuda_fp16.h>
#include <cstdint>
#include <math.h>

#define SEQ    2048
#define DMODEL 5120
#define NHEAD  40
#define HDIM   128
#define NQKV   15360
#define K2Q    10240            // 2 * 5120 expanded K
#define ATT_SCALE 0.08838834764831845f

// ---------------------------------------------------------------------------
// Scratch (device globals — no allocation allowed)
// ---------------------------------------------------------------------------
__device__ __align__(256) float g_qkv[(size_t)SEQ * NQKV];
__device__ __align__(256) float g_q[(size_t)SEQ * DMODEL];     // [H,S,D]
__device__ __align__(256) float g_k[(size_t)SEQ * DMODEL];     // [H,S,D]
__device__ __align__(256) float g_ctx[(size_t)SEQ * DMODEL];
__device__ __align__(256) __half g_a2[(size_t)SEQ * K2Q];          // act [M, 2K] (hi,lo)
__device__ __align__(256) __half g_w2qkv[(size_t)NQKV * K2Q];      // w_qkv^T [N, 2K] (hi,hi)
__device__ __align__(256) __half g_w2out[(size_t)DMODEL * K2Q];    // w_out^T [N, 2K] (hi,hi)

// ---------------------------------------------------------------------------
__device__ __forceinline__ uint32_t smem_u32(const void* p) {
    uint32_t a;
    asm("{ .reg .u64 t; cvta.to.shared.u64 t, %1; cvt.u32.u64 %0, t; }" : "=r"(a) : "l"(p));
    return a;
}
#define CP_ASYNC16(dst, src) \
    asm volatile("cp.async.cg.shared.global [%0], [%1], 16;" :: "r"(dst), "l"(src) : "memory")
#define CP_COMMIT()  asm volatile("cp.async.commit_group;" ::: "memory")
#define CP_WAIT1()   asm volatile("cp.async.wait_group 1;" ::: "memory")

// swizzled byte offset inside one 128x(64 half) tile: row-XOR on 16B chunks
__device__ __forceinline__ uint32_t swz(int r, int kh) {
    uint32_t byte = (uint32_t)kh * 2u;
    uint32_t c = byte >> 4;
    return (uint32_t)r * 128u + (((c ^ ((uint32_t)r & 7u)) << 4) | (byte & 15u));
}

__device__ __forceinline__ void mma16816(float* d, const uint32_t* a, const uint32_t* b) {
    asm volatile(
        "mma.sync.aligned.m16n8k16.row.col.f32.f16.f16.f32 "
        "{%0,%1,%2,%3}, {%4,%5,%6,%7}, {%8,%9}, {%0,%1,%2,%3};"
        : "+f"(d[0]), "+f"(d[1]), "+f"(d[2]), "+f"(d[3])
        : "r"(a[0]), "r"(a[1]), "r"(a[2]), "r"(a[3]), "r"(b[0]), "r"(b[1]));
}

// ---------------------------------------------------------------------------
// conv_act: [M,K] fp32 -> [M,2K] fp16 pattern (hi, lo) per element
// ---------------------------------------------------------------------------
__global__ __launch_bounds__(256) void conv_act(const float* __restrict__ in,
                                                __half* __restrict__ out, int n8)
{
    int t = blockIdx.x * 256 + threadIdx.x;
    if (t >= n8) return;
    size_t k = (size_t)t * 8;
    float4 a = *(const float4*)(in + k);
    float4 b = *(const float4*)(in + k + 4);
    float v[8] = {a.x, a.y, a.z, a.w, b.x, b.y, b.z, b.w};
    __half o[16];
#pragma unroll
    for (int i = 0; i < 8; i++) {
        __half hi = __float2half_rn(v[i]);
        __half lo = __float2half_rn(v[i] - __half2float(hi));
        o[2 * i] = hi; o[2 * i + 1] = lo;
    }
    uint4* dst = (uint4*)(out + k * 2);
    const uint4* src = (const uint4*)o;
    dst[0] = src[0]; dst[1] = src[1];
}

// ---------------------------------------------------------------------------
// conv_wt: [K,N] fp32 -> [N,2K] fp16 pattern (hi, hi)
// ---------------------------------------------------------------------------
__global__ __launch_bounds__(128) void conv_wt(const float* __restrict__ W,
                                               __half* __restrict__ Wt,
                                               int Kdim, int Ndim)
{
    __shared__ float tile[32][33];
    const int k0 = blockIdx.y * 32, n0 = blockIdx.x * 32;
    const int lane = threadIdx.x & 31, warp = threadIdx.x >> 5;
#pragma unroll
    for (int i = 0; i < 8; i++) {
        int kr = warp + i * 4;
        tile[kr][lane] = W[(size_t)(k0 + kr) * Ndim + n0 + lane];
    }
    __syncthreads();
    const int nl = threadIdx.x >> 2;
    const int ks = threadIdx.x & 3;
    __half o[16];
#pragma unroll
    for (int e = 0; e < 8; e++) {
        __half hi = __float2half_rn(tile[ks * 8 + e][nl]);
        o[2 * e] = hi; o[2 * e + 1] = hi;
    }
    uint4* dst = (uint4*)(Wt + (size_t)(n0 + nl) * (2 * (size_t)Kdim) + 2 * (k0 + ks * 8));
    const uint4* src = (const uint4*)o;
    dst[0] = src[0]; dst[1] = src[1];
}

// ---------------------------------------------------------------------------
// mma.sync GEMM: C[M,N] = A[M,K2] x B[N,K2]^T + bias
// CTA 128x128, BK=64 halves, 3-stage cp.async pipeline, 8 warps (4M x 2N),
// warp tile 32x64 (2 x 8 m16n8k16 tiles).
// ---------------------------------------------------------------------------
__global__ __launch_bounds__(256, 2) void gemm_mma(
    const __half* __restrict__ A, const __half* __restrict__ B,
    const float* __restrict__ bias, float* __restrict__ C, int N, int K2)
{
    extern __shared__ char smem[];
    const uint32_t sb = smem_u32(smem);
    const int tid = threadIdx.x;
    const int lane = tid & 31;
    const int wid = tid >> 5;
    const int wm = (wid & 3) * 32;          // warp M offset
    const int wn = (wid >> 2) * 64;         // warp N offset
    const uint32_t SSZ = 32768;             // stage: A 16K + B 16K

    const size_t arow0 = (size_t)blockIdx.x * 128;
    const size_t brow0 = (size_t)blockIdx.y * 128;
    const int NC = K2 / 64;

    auto load_stage = [&](int st, int kc) {
        const uint32_t ab = sb + st * SSZ;
#pragma unroll
        for (int i = 0; i < 4; i++) {
            int id = tid + i * 256;
            int row = id >> 3, c = id & 7;
            uint32_t dst = ab + (uint32_t)(row * 128) + (((uint32_t)(c ^ (row & 7))) << 4);
            CP_ASYNC16(dst, A + (arow0 + row) * (size_t)K2 + kc * 64 + c * 8);
        }
#pragma unroll
        for (int i = 0; i < 4; i++) {
            int id = tid + i * 256;
            int row = id >> 3, c = id & 7;
            uint32_t dst = ab + 16384u + (uint32_t)(row * 128) + (((uint32_t)(c ^ (row & 7))) << 4);
            CP_ASYNC16(dst, B + (brow0 + row) * (size_t)K2 + kc * 64 + c * 8);
        }
    };

    float acc[2][8][4];
#pragma unroll
    for (int i = 0; i < 2; i++)
#pragma unroll
        for (int j = 0; j < 8; j++)
#pragma unroll
            for (int e = 0; e < 4; e++) acc[i][j][e] = 0.f;

    load_stage(0, 0); CP_COMMIT();
    load_stage(1, 1); CP_COMMIT();

    const int g = lane >> 2;            // 0..7
    const int tig = lane & 3;           // 0..3

    for (int cc = 0; cc < NC; cc++) {
        CP_WAIT1();
        __syncthreads();
        if (cc + 2 < NC) load_stage((cc + 2) % 3, cc + 2);
        CP_COMMIT();                    // possibly-empty group keeps wait count aligned

        const char* Ab = smem + (cc % 3) * SSZ;
        const char* Bb = Ab + 16384;
#pragma unroll
        for (int ks = 0; ks < 4; ks++) {
            const int kf = ks * 16 + tig * 2;
            uint32_t a[2][4], b[8][2];
#pragma unroll
            for (int i = 0; i < 2; i++) {
                int r = wm + i * 16 + g;
                a[i][0] = *(const uint32_t*)(Ab + swz(r,     kf));
                a[i][1] = *(const uint32_t*)(Ab + swz(r + 8, kf));
                a[i][2] = *(const uint32_t*)(Ab + swz(r,     kf + 8));
                a[i][3] = *(const uint32_t*)(Ab + swz(r + 8, kf + 8));
            }
#pragma unroll
            for (int j = 0; j < 8; j++) {
                int n = wn + j * 8 + g;
                b[j][0] = *(const uint32_t*)(Bb + swz(n, kf));
                b[j][1] = *(const uint32_t*)(Bb + swz(n, kf + 8));
            }
#pragma unroll
            for (int i = 0; i < 2; i++)
#pragma unroll
                for (int j = 0; j < 8; j++)
                    mma16816(acc[i][j], a[i], b[j]);
        }
        __syncthreads();
    }

    // epilogue: direct global stores + bias
#pragma unroll
    for (int i = 0; i < 2; i++) {
        int r = (int)arow0 + wm + i * 16 + g;
#pragma unroll
        for (int j = 0; j < 8; j++) {
            int c = (int)brow0 + wn + j * 8 + tig * 2;
            float bx = bias[c], by = bias[c + 1];
            float2 v0 = {acc[i][j][0] + bx, acc[i][j][1] + by};
            float2 v1 = {acc[i][j][2] + bx, acc[i][j][3] + by};
            *(float2*)(C + (size_t)r * N + c) = v0;
            *(float2*)(C + (size_t)(r + 8) * N + c) = v1;
        }
    }
}

// ---------------------------------------------------------------------------
// Fused RMSNorm + RoPE (unchanged, passed R1)
// ---------------------------------------------------------------------------
__global__ __launch_bounds__(256) void norm_rope(
    const float* __restrict__ cosp, const float* __restrict__ sinp,
    const float* __restrict__ wq, const float* __restrict__ wk)
{
    const int s = blockIdx.x;
    const int tid = threadIdx.x;
    const float* qrow = g_qkv + (size_t)s * NQKV;
    const float* krow = qrow + DMODEL;

    float sq = 0.f, sk = 0.f;
    for (int i = tid; i < DMODEL; i += 256) {
        float a = qrow[i]; sq += a * a;
        float b = krow[i]; sk += b * b;
    }
#pragma unroll
    for (int off = 16; off; off >>= 1) {
        sq += __shfl_xor_sync(0xffffffffu, sq, off);
        sk += __shfl_xor_sync(0xffffffffu, sk, off);
    }
    __shared__ float shq[8], shk[8];
    if ((tid & 31) == 0) { shq[tid >> 5] = sq; shk[tid >> 5] = sk; }
    __syncthreads();
    float tq = 0.f, tk = 0.f;
#pragma unroll
    for (int i = 0; i < 8; i++) { tq += shq[i]; tk += shk[i]; }
    const float rq = rsqrtf(tq / DMODEL + 1e-6f);
    const float rk = rsqrtf(tk / DMODEL + 1e-6f);

    for (int p = tid; p < DMODEL / 2; p += 256) {
        const int i0 = 2 * p;
        const int h = i0 >> 7;
        const int dl = i0 & 127;
        const float c  = cosp[s * HDIM + dl];
        const float sn = sinp[s * HDIM + dl];
        float q0 = qrow[i0] * rq * wq[i0];
        float q1 = qrow[i0 + 1] * rq * wq[i0 + 1];
        float k0 = krow[i0] * rk * wk[i0];
        float k1 = krow[i0 + 1] * rk * wk[i0 + 1];
        const size_t o = (size_t)h * SEQ * HDIM + (size_t)s * HDIM + dl;
        g_q[o]     = q0 * c - q1 * sn;
        g_q[o + 1] = q0 * sn + q1 * c;
        g_k[o]     = k0 * c - k1 * sn;
        g_k[o + 1] = k0 * sn + k1 * c;
    }
}

// ---------------------------------------------------------------------------
// Flash-style attention, fp32 (unchanged, passed R1)
// ---------------------------------------------------------------------------
__global__ __launch_bounds__(256) void flash_attn(float* __restrict__ ctx)
{
    extern __shared__ float sm[];
    float* Qs = sm;
    float* Ks = sm + 8192;
    float* Vs = sm + 16384;
    float* Ps = sm + 24576;

    const int qt = blockIdx.x;
    const int h  = blockIdx.y;
    const int tid = threadIdx.x;
    const int tx = tid & 15;
    const int ty = tid >> 4;
    const int q0 = qt * 64;

    const float* Qh = g_q + (size_t)h * SEQ * HDIM;
    const float* Kh = g_k + (size_t)h * SEQ * HDIM;
    const float* Vg = g_qkv + 2 * DMODEL + h * HDIM;

    for (int l = tid; l < 64 * 32; l += 256) {
        int r = l >> 5, c4 = (l & 31) * 4;
        float4 v = *(const float4*)(Qh + (size_t)(q0 + r) * HDIM + c4);
        Qs[(c4 + 0) * 64 + r] = v.x;
        Qs[(c4 + 1) * 64 + r] = v.y;
        Qs[(c4 + 2) * 64 + r] = v.z;
        Qs[(c4 + 3) * 64 + r] = v.w;
    }

    float o[4][8];
#pragma unroll
    for (int i = 0; i < 4; i++)
#pragma unroll
        for (int j = 0; j < 8; j++) o[i][j] = 0.f;
    float m[4] = {-1e30f, -1e30f, -1e30f, -1e30f};
    float lsum[4] = {0.f, 0.f, 0.f, 0.f};

    for (int kt = 0; kt < SEQ / 64; kt++) {
        __syncthreads();
        for (int l = tid; l < 64 * 32; l += 256) {
            int r = l >> 5, c4 = (l & 31) * 4;
            float4 v = *(const float4*)(Kh + (size_t)(kt * 64 + r) * HDIM + c4);
            Ks[(c4 + 0) * 64 + r] = v.x;
            Ks[(c4 + 1) * 64 + r] = v.y;
            Ks[(c4 + 2) * 64 + r] = v.z;
            Ks[(c4 + 3) * 64 + r] = v.w;
            float4 w = *(const float4*)(Vg + (size_t)(kt * 64 + r) * NQKV + c4);
            *(float4*)(Vs + r * 128 + c4) = w;
        }
        __syncthreads();

        float sc[4][4];
#pragma unroll
        for (int i = 0; i < 4; i++)
#pragma unroll
            for (int j = 0; j < 4; j++) sc[i][j] = 0.f;
        for (int kk = 0; kk < HDIM; kk++) {
            float4 qa = *(float4*)(Qs + kk * 64 + ty * 4);
            float4 kb = *(float4*)(Ks + kk * 64 + tx * 4);
            float a[4] = {qa.x, qa.y, qa.z, qa.w};
            float b[4] = {kb.x, kb.y, kb.z, kb.w};
#pragma unroll
            for (int i = 0; i < 4; i++)
#pragma unroll
                for (int j = 0; j < 4; j++)
                    sc[i][j] = fmaf(a[i], b[j], sc[i][j]);
        }

#pragma unroll
        for (int i = 0; i < 4; i++) {
            float mx = -1e30f;
#pragma unroll
            for (int j = 0; j < 4; j++) {
                sc[i][j] *= ATT_SCALE;
                mx = fmaxf(mx, sc[i][j]);
            }
#pragma unroll
            for (int off = 8; off; off >>= 1)
                mx = fmaxf(mx, __shfl_xor_sync(0xffffffffu, mx, off, 16));
            float mnew = fmaxf(m[i], mx);
            float fs = __expf(m[i] - mnew);
            float ps[4], psum = 0.f;
#pragma unroll
            for (int j = 0; j < 4; j++) {
                ps[j] = __expf(sc[i][j] - mnew);
                psum += ps[j];
            }
#pragma unroll
            for (int off = 8; off; off >>= 1)
                psum += __shfl_xor_sync(0xffffffffu, psum, off, 16);
            lsum[i] = lsum[i] * fs + psum;
            m[i] = mnew;
#pragma unroll
            for (int c = 0; c < 8; c++) o[i][c] *= fs;
#pragma unroll
            for (int j = 0; j < 4; j++)
                Ps[(ty * 4 + i) * 64 + tx * 4 + j] = ps[j];
        }
        __syncthreads();

        for (int kk = 0; kk < 64; kk++) {
            float4 v0 = *(float4*)(Vs + kk * 128 + tx * 4);
            float4 v1 = *(float4*)(Vs + kk * 128 + 64 + tx * 4);
#pragma unroll
            for (int i = 0; i < 4; i++) {
                float p = Ps[(ty * 4 + i) * 64 + kk];
                o[i][0] = fmaf(p, v0.x, o[i][0]);
                o[i][1] = fmaf(p, v0.y, o[i][1]);
                o[i][2] = fmaf(p, v0.z, o[i][2]);
                o[i][3] = fmaf(p, v0.w, o[i][3]);
                o[i][4] = fmaf(p, v1.x, o[i][4]);
                o[i][5] = fmaf(p, v1.y, o[i][5]);
                o[i][6] = fmaf(p, v1.z, o[i][6]);
                o[i][7] = fmaf(p, v1.w, o[i][7]);
            }
        }
    }

#pragma unroll
    for (int i = 0; i < 4; i++) {
        float inv = 1.0f / lsum[i];
        int r = q0 + ty * 4 + i;
        size_t base = (size_t)r * DMODEL + h * HDIM;
#pragma unroll
        for (int j = 0; j < 4; j++) {
            ctx[base + tx * 4 + j]      = o[i][j] * inv;
            ctx[base + 64 + tx * 4 + j] = o[i][4 + j] * inv;
        }
    }
}

// ---------------------------------------------------------------------------
extern "C" void kernel_launch(void* const* d_in, const int* in_sizes, int n_in,
                              void* d_out, int out_size)
{
    const float* x     = (const float*)d_in[0];
    const float* cosp  = (const float*)d_in[1];
    const float* sinp  = (const float*)d_in[2];
    const float* w_qkv = (const float*)d_in[3];
    const float* b_qkv = (const float*)d_in[4];
    const float* wq    = (const float*)d_in[5];
    const float* wk    = (const float*)d_in[6];
    const float* w_out = (const float*)d_in[7];
    const float* b_out = (const float*)d_in[8];
    float* out = (float*)d_out;

    float *qkv_p, *ctx_p;
    __half *a2_p, *w2qkv_p, *w2out_p;
    cudaGetSymbolAddress((void**)&qkv_p,   g_qkv);
    cudaGetSymbolAddress((void**)&ctx_p,   g_ctx);
    cudaGetSymbolAddress((void**)&a2_p,    g_a2);
    cudaGetSymbolAddress((void**)&w2qkv_p, g_w2qkv);
    cudaGetSymbolAddress((void**)&w2out_p, g_w2out);

    const int GEMM_SMEM = 3 * 32768;   // 98304
    cudaFuncSetAttribute(gemm_mma, cudaFuncAttributeMaxDynamicSharedMemorySize, GEMM_SMEM);
    cudaFuncSetAttribute(flash_attn, cudaFuncAttributeMaxDynamicSharedMemorySize, 114688);

    // split-convert weights + activations
    conv_wt<<<dim3(NQKV / 32, DMODEL / 32), 128>>>(w_qkv, w2qkv_p, DMODEL, NQKV);
    conv_act<<<(SEQ * DMODEL / 8 + 255) / 256, 256>>>(x, a2_p, SEQ * DMODEL / 8);

    // QKV projection (tensor cores)
    gemm_mma<<<dim3(SEQ / 128, NQKV / 128), 256, GEMM_SMEM>>>(
        a2_p, w2qkv_p, b_qkv, qkv_p, NQKV, K2Q);

    // RMSNorm + RoPE
    norm_rope<<<SEQ, 256>>>(cosp, sinp, wq, wk);

    // attention
    flash_attn<<<dim3(SEQ / 64, NHEAD), 256, 114688>>>(ctx_p);

    // output projection (tensor cores)
    conv_wt<<<dim3(DMODEL / 32, DMODEL / 32), 128>>>(w_out, w2out_p, DMODEL, DMODEL);
    conv_act<<<(SEQ * DMODEL / 8 + 255) / 256, 256>>>(ctx_p, a2_p, SEQ * DMODEL / 8);
    gemm_mma<<<dim3(SEQ / 128, DMODEL / 128), 256, GEMM_SMEM>>>(
        a2_p, w2out_p, b_out, out, DMODEL, K2Q);
}

// round 6
// speedup vs baseline: 4.3983x; 1.9646x over previous
#include <cuda_runtime.h>
#include <cuda_fp16.h>
#include <cstdint>
#include <math.h>

#define SEQ    2048
#define DMODEL 5120
#define NHEAD  40
#define HDIM   128
#define NQKV   15360
#define K2Q    10240            // 2 * 5120 expanded K
#define ATT_SCALE 0.08838834764831845f

// ---------------------------------------------------------------------------
// Scratch (device globals — no allocation allowed)
// ---------------------------------------------------------------------------
__device__ __align__(256) float  g_qkv[(size_t)SEQ * NQKV];
__device__ __align__(256) __half g_a2[(size_t)SEQ * K2Q];          // act [M,2K] (hi,lo); reused for x and ctx
__device__ __align__(256) __half g_w2qkv[(size_t)NQKV * K2Q];      // w_qkv^T [N,2K] (hi,hi)
__device__ __align__(256) __half g_w2out[(size_t)DMODEL * K2Q];    // w_out^T [N,2K] (hi,hi)
__device__ __align__(256) __half g_q2[(size_t)NHEAD * SEQ * 256];  // Q [H,S,256] (hi,lo)
__device__ __align__(256) __half g_k2[(size_t)NHEAD * SEQ * 256];  // K [H,S,256] (hi,hi)
__device__ __align__(256) __half g_vt[(size_t)NHEAD * HDIM * SEQ]; // V^T [H,D,S] fp16

// ---------------------------------------------------------------------------
__device__ __forceinline__ uint32_t smem_u32(const void* p) {
    uint32_t a;
    asm("{ .reg .u64 t; cvta.to.shared.u64 t, %1; cvt.u32.u64 %0, t; }" : "=r"(a) : "l"(p));
    return a;
}
#define CP_ASYNC16(dst, src) \
    asm volatile("cp.async.cg.shared.global [%0], [%1], 16;" :: "r"(dst), "l"(src) : "memory")
#define CP_COMMIT()  asm volatile("cp.async.commit_group;" ::: "memory")
#define CP_WAIT1()   asm volatile("cp.async.wait_group 1;" ::: "memory")
#define CP_WAIT0()   asm volatile("cp.async.wait_group 0;" ::: "memory")

// swizzled byte offset in a row of 64 halves (128B)
__device__ __forceinline__ uint32_t swz(int r, int kh) {
    uint32_t byte = (uint32_t)kh * 2u;
    uint32_t c = byte >> 4;
    return (uint32_t)r * 128u + (((c ^ ((uint32_t)r & 7u)) << 4) | (byte & 15u));
}
// swizzled byte offset in a row of 256 halves (512B)
__device__ __forceinline__ uint32_t swz512(int r, int kh) {
    uint32_t byte = (uint32_t)kh * 2u;
    uint32_t c = byte >> 4;
    return (uint32_t)r * 512u + (((c ^ ((uint32_t)r & 7u)) << 4) | (byte & 15u));
}

__device__ __forceinline__ void mma16816(float* d, const uint32_t* a, const uint32_t* b) {
    asm volatile(
        "mma.sync.aligned.m16n8k16.row.col.f32.f16.f16.f32 "
        "{%0,%1,%2,%3}, {%4,%5,%6,%7}, {%8,%9}, {%0,%1,%2,%3};"
        : "+f"(d[0]), "+f"(d[1]), "+f"(d[2]), "+f"(d[3])
        : "r"(a[0]), "r"(a[1]), "r"(a[2]), "r"(a[3]), "r"(b[0]), "r"(b[1]));
}

// ---------------------------------------------------------------------------
// conv_act: [M,K] fp32 -> [M,2K] fp16 pattern (hi, lo)
// ---------------------------------------------------------------------------
__global__ __launch_bounds__(256) void conv_act(const float* __restrict__ in,
                                                __half* __restrict__ out, int n8)
{
    int t = blockIdx.x * 256 + threadIdx.x;
    if (t >= n8) return;
    size_t k = (size_t)t * 8;
    float4 a = *(const float4*)(in + k);
    float4 b = *(const float4*)(in + k + 4);
    float v[8] = {a.x, a.y, a.z, a.w, b.x, b.y, b.z, b.w};
    __half o[16];
#pragma unroll
    for (int i = 0; i < 8; i++) {
        __half hi = __float2half_rn(v[i]);
        __half lo = __float2half_rn(v[i] - __half2float(hi));
        o[2 * i] = hi; o[2 * i + 1] = lo;
    }
    uint4* dst = (uint4*)(out + k * 2);
    const uint4* src = (const uint4*)o;
    dst[0] = src[0]; dst[1] = src[1];
}

// ---------------------------------------------------------------------------
// conv_wt: [K,N] fp32 -> [N,2K] fp16 pattern (hi, hi)
// ---------------------------------------------------------------------------
__global__ __launch_bounds__(128) void conv_wt(const float* __restrict__ W,
                                               __half* __restrict__ Wt,
                                               int Kdim, int Ndim)
{
    __shared__ float tile[32][33];
    const int k0 = blockIdx.y * 32, n0 = blockIdx.x * 32;
    const int lane = threadIdx.x & 31, warp = threadIdx.x >> 5;
#pragma unroll
    for (int i = 0; i < 8; i++) {
        int kr = warp + i * 4;
        tile[kr][lane] = W[(size_t)(k0 + kr) * Ndim + n0 + lane];
    }
    __syncthreads();
    const int nl = threadIdx.x >> 2;
    const int ks = threadIdx.x & 3;
    __half o[16];
#pragma unroll
    for (int e = 0; e < 8; e++) {
        __half hi = __float2half_rn(tile[ks * 8 + e][nl]);
        o[2 * e] = hi; o[2 * e + 1] = hi;
    }
    uint4* dst = (uint4*)(Wt + (size_t)(n0 + nl) * (2 * (size_t)Kdim) + 2 * (k0 + ks * 8));
    const uint4* src = (const uint4*)o;
    dst[0] = src[0]; dst[1] = src[1];
}

// ---------------------------------------------------------------------------
// conv_vt: V [S, d@qkv] fp32 -> V^T [H, D, S] fp16
// block (32x8)=256 threads, tile 32 s x 32 d.
// ---------------------------------------------------------------------------
__global__ __launch_bounds__(256) void conv_vt()
{
    __shared__ float t[32][33];
    const int s0  = blockIdx.x * 32;
    const int d0g = blockIdx.y * 32;               // global d 0..5119 (tile within one head)
    const int h   = d0g >> 7;
    const int dh0 = d0g & 127;
    const int lx = threadIdx.x & 31, ly = threadIdx.x >> 5;
    const float* src = g_qkv + 2 * DMODEL + (size_t)h * HDIM + dh0;
#pragma unroll
    for (int r = 0; r < 4; r++) {
        int srow = ly + r * 8;
        t[srow][lx] = src[(size_t)(s0 + srow) * NQKV + lx];
    }
    __syncthreads();
#pragma unroll
    for (int r = 0; r < 4; r++) {
        int dd = ly + r * 8;
        g_vt[(size_t)(d0g + dd) * SEQ + s0 + lx] = __float2half_rn(t[lx][dd]);
    }
}

// ---------------------------------------------------------------------------
// mma.sync GEMM (unchanged from R3, passing): C = A[M,K2] x B[N,K2]^T + bias
// ---------------------------------------------------------------------------
__global__ __launch_bounds__(256, 2) void gemm_mma(
    const __half* __restrict__ A, const __half* __restrict__ B,
    const float* __restrict__ bias, float* __restrict__ C, int N, int K2)
{
    extern __shared__ char smem[];
    const uint32_t sb = smem_u32(smem);
    const int tid = threadIdx.x;
    const int lane = tid & 31;
    const int wid = tid >> 5;
    const int wm = (wid & 3) * 32;
    const int wn = (wid >> 2) * 64;
    const uint32_t SSZ = 32768;

    const size_t arow0 = (size_t)blockIdx.x * 128;
    const size_t brow0 = (size_t)blockIdx.y * 128;
    const int NC = K2 / 64;

    auto load_stage = [&](int st, int kc) {
        const uint32_t ab = sb + st * SSZ;
#pragma unroll
        for (int i = 0; i < 4; i++) {
            int id = tid + i * 256;
            int row = id >> 3, c = id & 7;
            uint32_t dst = ab + (uint32_t)(row * 128) + (((uint32_t)(c ^ (row & 7))) << 4);
            CP_ASYNC16(dst, A + (arow0 + row) * (size_t)K2 + kc * 64 + c * 8);
        }
#pragma unroll
        for (int i = 0; i < 4; i++) {
            int id = tid + i * 256;
            int row = id >> 3, c = id & 7;
            uint32_t dst = ab + 16384u + (uint32_t)(row * 128) + (((uint32_t)(c ^ (row & 7))) << 4);
            CP_ASYNC16(dst, B + (brow0 + row) * (size_t)K2 + kc * 64 + c * 8);
        }
    };

    float acc[2][8][4];
#pragma unroll
    for (int i = 0; i < 2; i++)
#pragma unroll
        for (int j = 0; j < 8; j++)
#pragma unroll
            for (int e = 0; e < 4; e++) acc[i][j][e] = 0.f;

    load_stage(0, 0); CP_COMMIT();
    load_stage(1, 1); CP_COMMIT();

    const int g = lane >> 2;
    const int tig = lane & 3;

    for (int cc = 0; cc < NC; cc++) {
        CP_WAIT1();
        __syncthreads();
        if (cc + 2 < NC) load_stage((cc + 2) % 3, cc + 2);
        CP_COMMIT();

        const char* Ab = smem + (cc % 3) * SSZ;
        const char* Bb = Ab + 16384;
#pragma unroll
        for (int ks = 0; ks < 4; ks++) {
            const int kf = ks * 16 + tig * 2;
            uint32_t a[2][4], b[8][2];
#pragma unroll
            for (int i = 0; i < 2; i++) {
                int r = wm + i * 16 + g;
                a[i][0] = *(const uint32_t*)(Ab + swz(r,     kf));
                a[i][1] = *(const uint32_t*)(Ab + swz(r + 8, kf));
                a[i][2] = *(const uint32_t*)(Ab + swz(r,     kf + 8));
                a[i][3] = *(const uint32_t*)(Ab + swz(r + 8, kf + 8));
            }
#pragma unroll
            for (int j = 0; j < 8; j++) {
                int n = wn + j * 8 + g;
                b[j][0] = *(const uint32_t*)(Bb + swz(n, kf));
                b[j][1] = *(const uint32_t*)(Bb + swz(n, kf + 8));
            }
#pragma unroll
            for (int i = 0; i < 2; i++)
#pragma unroll
                for (int j = 0; j < 8; j++)
                    mma16816(acc[i][j], a[i], b[j]);
        }
        __syncthreads();
    }

#pragma unroll
    for (int i = 0; i < 2; i++) {
        int r = (int)arow0 + wm + i * 16 + g;
#pragma unroll
        for (int j = 0; j < 8; j++) {
            int c = (int)brow0 + wn + j * 8 + tig * 2;
            float bx = bias[c], by = bias[c + 1];
            float2 v0 = {acc[i][j][0] + bx, acc[i][j][1] + by};
            float2 v1 = {acc[i][j][2] + bx, acc[i][j][3] + by};
            *(float2*)(C + (size_t)r * N + c) = v0;
            *(float2*)(C + (size_t)(r + 8) * N + c) = v1;
        }
    }
}

// ---------------------------------------------------------------------------
// RMSNorm + RoPE -> fp16 Q' (hi,lo) and K' (hi,hi), layout [H,S,256]
// ---------------------------------------------------------------------------
__global__ __launch_bounds__(256) void norm_rope(
    const float* __restrict__ cosp, const float* __restrict__ sinp,
    const float* __restrict__ wq, const float* __restrict__ wk)
{
    const int s = blockIdx.x;
    const int tid = threadIdx.x;
    const float* qrow = g_qkv + (size_t)s * NQKV;
    const float* krow = qrow + DMODEL;

    float sq = 0.f, sk = 0.f;
    for (int i = tid; i < DMODEL; i += 256) {
        float a = qrow[i]; sq += a * a;
        float b = krow[i]; sk += b * b;
    }
#pragma unroll
    for (int off = 16; off; off >>= 1) {
        sq += __shfl_xor_sync(0xffffffffu, sq, off);
        sk += __shfl_xor_sync(0xffffffffu, sk, off);
    }
    __shared__ float shq[8], shk[8];
    if ((tid & 31) == 0) { shq[tid >> 5] = sq; shk[tid >> 5] = sk; }
    __syncthreads();
    float tq = 0.f, tk = 0.f;
#pragma unroll
    for (int i = 0; i < 8; i++) { tq += shq[i]; tk += shk[i]; }
    const float rq = rsqrtf(tq / DMODEL + 1e-6f);
    const float rk = rsqrtf(tk / DMODEL + 1e-6f);

    for (int p = tid; p < DMODEL / 2; p += 256) {
        const int i0 = 2 * p;
        const int h = i0 >> 7;
        const int dl = i0 & 127;
        const float c  = cosp[s * HDIM + dl];
        const float sn = sinp[s * HDIM + dl];
        float q0 = qrow[i0] * rq * wq[i0];
        float q1 = qrow[i0 + 1] * rq * wq[i0 + 1];
        float k0 = krow[i0] * rk * wk[i0];
        float k1 = krow[i0 + 1] * rk * wk[i0 + 1];
        float qe = q0 * c - q1 * sn;
        float qo = q0 * sn + q1 * c;
        float ke = k0 * c - k1 * sn;
        float ko = k0 * sn + k1 * c;

        const size_t base = ((size_t)h * SEQ + s) * 256 + 2 * dl;
        __half qeh = __float2half_rn(qe);
        __half qel = __float2half_rn(qe - __half2float(qeh));
        __half qoh = __float2half_rn(qo);
        __half qol = __float2half_rn(qo - __half2float(qoh));
        __half qv[4] = {qeh, qel, qoh, qol};
        *(uint2*)(g_q2 + base) = *(const uint2*)qv;

        __half keh = __float2half_rn(ke);
        __half koh = __float2half_rn(ko);
        __half kv[4] = {keh, keh, koh, koh};
        *(uint2*)(g_k2 + base) = *(const uint2*)kv;
    }
}

// ---------------------------------------------------------------------------
// Tensor-core flash attention. CTA: 64 q rows x 1 head, 4 warps (16 m each).
// smem: Q'[64][256h swz] 32KB @0, K'[64][256h swz] 32KB @32768,
//       Vt[128][64h swz] 16KB @65536. Total 81920.
// Output: ctx written split (hi,lo) directly into g_a2 [S, 2*DMODEL].
// ---------------------------------------------------------------------------
__global__ __launch_bounds__(128, 2) void flash_tc()
{
    extern __shared__ char smem[];
    const uint32_t sb = smem_u32(smem);
    const int h  = blockIdx.y;
    const int qt = blockIdx.x;
    const int tid = threadIdx.x;
    const int lane = tid & 31;
    const int wid = tid >> 5;
    const int g = lane >> 2;
    const int tig = lane & 3;

    const __half* Qg = g_q2 + ((size_t)h * SEQ + qt * 64) * 256;
    const __half* Kg = g_k2 + (size_t)h * SEQ * 256;
    const __half* Vg = g_vt + (size_t)h * HDIM * SEQ;

    // load Q' once
#pragma unroll
    for (int i = 0; i < 16; i++) {
        int id = tid + i * 128;
        int r = id >> 5, c = id & 31;
        uint32_t dst = sb + (uint32_t)(r * 512) + (((uint32_t)(c ^ (r & 7))) << 4);
        CP_ASYNC16(dst, Qg + (size_t)r * 256 + c * 8);
    }
    CP_COMMIT();

    float o[16][4];
#pragma unroll
    for (int jd = 0; jd < 16; jd++)
#pragma unroll
        for (int e = 0; e < 4; e++) o[jd][e] = 0.f;
    float mA = -1e30f, mB = -1e30f, lA = 0.f, lB = 0.f;

    for (int kt = 0; kt < SEQ / 64; kt++) {
        __syncthreads();     // previous iter's smem reads complete
        // load K' tile
#pragma unroll
        for (int i = 0; i < 16; i++) {
            int id = tid + i * 128;
            int r = id >> 5, c = id & 31;
            uint32_t dst = sb + 32768u + (uint32_t)(r * 512) + (((uint32_t)(c ^ (r & 7))) << 4);
            CP_ASYNC16(dst, Kg + (size_t)(kt * 64 + r) * 256 + c * 8);
        }
        // load Vt tile (rows = d 0..127, 64 keys each)
#pragma unroll
        for (int i = 0; i < 8; i++) {
            int id = tid + i * 128;
            int r = id >> 3, c = id & 7;
            uint32_t dst = sb + 65536u + (uint32_t)(r * 128) + (((uint32_t)(c ^ (r & 7))) << 4);
            CP_ASYNC16(dst, Vg + (size_t)r * SEQ + kt * 64 + c * 8);
        }
        CP_COMMIT();
        CP_WAIT0();
        __syncthreads();

        // ---- S = Q' K'^T (k-dim 256) ----
        float sacc[8][4];
#pragma unroll
        for (int j = 0; j < 8; j++)
#pragma unroll
            for (int e = 0; e < 4; e++) sacc[j][e] = 0.f;

        const char* Qb = smem;
        const char* Kb = smem + 32768;
        const char* Vb = smem + 65536;
        const int r0 = wid * 16 + g;
#pragma unroll
        for (int ks = 0; ks < 16; ks++) {
            const int kf = ks * 16 + tig * 2;
            uint32_t a[4];
            a[0] = *(const uint32_t*)(Qb + swz512(r0,     kf));
            a[1] = *(const uint32_t*)(Qb + swz512(r0 + 8, kf));
            a[2] = *(const uint32_t*)(Qb + swz512(r0,     kf + 8));
            a[3] = *(const uint32_t*)(Qb + swz512(r0 + 8, kf + 8));
#pragma unroll
            for (int j = 0; j < 8; j++) {
                int key = 8 * j + g;
                uint32_t b[2];
                b[0] = *(const uint32_t*)(Kb + swz512(key, kf));
                b[1] = *(const uint32_t*)(Kb + swz512(key, kf + 8));
                mma16816(sacc[j], a, b);
            }
        }

        // ---- online softmax (rows r0 and r0+8) ----
        float mxA = -1e30f, mxB = -1e30f;
#pragma unroll
        for (int j = 0; j < 8; j++) {
            sacc[j][0] *= ATT_SCALE; sacc[j][1] *= ATT_SCALE;
            sacc[j][2] *= ATT_SCALE; sacc[j][3] *= ATT_SCALE;
            mxA = fmaxf(mxA, fmaxf(sacc[j][0], sacc[j][1]));
            mxB = fmaxf(mxB, fmaxf(sacc[j][2], sacc[j][3]));
        }
        mxA = fmaxf(mxA, __shfl_xor_sync(0xffffffffu, mxA, 1));
        mxA = fmaxf(mxA, __shfl_xor_sync(0xffffffffu, mxA, 2));
        mxB = fmaxf(mxB, __shfl_xor_sync(0xffffffffu, mxB, 1));
        mxB = fmaxf(mxB, __shfl_xor_sync(0xffffffffu, mxB, 2));
        const float mnA = fmaxf(mA, mxA);
        const float mnB = fmaxf(mB, mxB);
        const float fsA = __expf(mA - mnA);
        const float fsB = __expf(mB - mnB);
        float psA = 0.f, psB = 0.f;
        uint32_t pA[8], pB[8];
#pragma unroll
        for (int j = 0; j < 8; j++) {
            float p0 = __expf(sacc[j][0] - mnA);
            float p1 = __expf(sacc[j][1] - mnA);
            float p2 = __expf(sacc[j][2] - mnB);
            float p3 = __expf(sacc[j][3] - mnB);
            psA += p0 + p1; psB += p2 + p3;
            __half2 hA = __floats2half2_rn(p0, p1);
            __half2 hB = __floats2half2_rn(p2, p3);
            pA[j] = *(uint32_t*)&hA;
            pB[j] = *(uint32_t*)&hB;
        }
        psA += __shfl_xor_sync(0xffffffffu, psA, 1);
        psA += __shfl_xor_sync(0xffffffffu, psA, 2);
        psB += __shfl_xor_sync(0xffffffffu, psB, 1);
        psB += __shfl_xor_sync(0xffffffffu, psB, 2);
        lA = lA * fsA + psA;
        lB = lB * fsB + psB;
        mA = mnA; mB = mnB;
#pragma unroll
        for (int jd = 0; jd < 16; jd++) {
            o[jd][0] *= fsA; o[jd][1] *= fsA;
            o[jd][2] *= fsB; o[jd][3] *= fsB;
        }

        // ---- O += P V^T (k-dim 64 keys) ----
#pragma unroll
        for (int kk = 0; kk < 4; kk++) {
            uint32_t a2[4] = {pA[2 * kk], pB[2 * kk], pA[2 * kk + 1], pB[2 * kk + 1]};
            const int kf = kk * 16 + tig * 2;
#pragma unroll
            for (int jd = 0; jd < 16; jd++) {
                int d = 8 * jd + g;
                uint32_t b[2];
                b[0] = *(const uint32_t*)(Vb + swz(d, kf));
                b[1] = *(const uint32_t*)(Vb + swz(d, kf + 8));
                mma16816(o[jd], a2, b);
            }
        }
    }

    // ---- epilogue: split (hi,lo) fp16 into g_a2 [S, 2*DMODEL] ----
    const float invA = 1.0f / lA;
    const float invB = 1.0f / lB;
    const int rA = qt * 64 + wid * 16 + g;
    const int rB = rA + 8;
#pragma unroll
    for (int jd = 0; jd < 16; jd++) {
        const int c = 8 * jd + 2 * tig;               // d within head
        const size_t colh = 2 * ((size_t)h * HDIM + c);
        float vA0 = o[jd][0] * invA, vA1 = o[jd][1] * invA;
        float vB0 = o[jd][2] * invB, vB1 = o[jd][3] * invB;
        __half wa[4], wb[4];
        wa[0] = __float2half_rn(vA0); wa[1] = __float2half_rn(vA0 - __half2float(wa[0]));
        wa[2] = __float2half_rn(vA1); wa[3] = __float2half_rn(vA1 - __half2float(wa[2]));
        wb[0] = __float2half_rn(vB0); wb[1] = __float2half_rn(vB0 - __half2float(wb[0]));
        wb[2] = __float2half_rn(vB1); wb[3] = __float2half_rn(vB1 - __half2float(wb[2]));
        *(uint2*)(g_a2 + (size_t)rA * K2Q + colh) = *(const uint2*)wa;
        *(uint2*)(g_a2 + (size_t)rB * K2Q + colh) = *(const uint2*)wb;
    }
}

// ---------------------------------------------------------------------------
extern "C" void kernel_launch(void* const* d_in, const int* in_sizes, int n_in,
                              void* d_out, int out_size)
{
    const float* x     = (const float*)d_in[0];
    const float* cosp  = (const float*)d_in[1];
    const float* sinp  = (const float*)d_in[2];
    const float* w_qkv = (const float*)d_in[3];
    const float* b_qkv = (const float*)d_in[4];
    const float* wq    = (const float*)d_in[5];
    const float* wk    = (const float*)d_in[6];
    const float* w_out = (const float*)d_in[7];
    const float* b_out = (const float*)d_in[8];
    float* out = (float*)d_out;

    float* qkv_p;
    __half *a2_p, *w2qkv_p, *w2out_p;
    cudaGetSymbolAddress((void**)&qkv_p,   g_qkv);
    cudaGetSymbolAddress((void**)&a2_p,    g_a2);
    cudaGetSymbolAddress((void**)&w2qkv_p, g_w2qkv);
    cudaGetSymbolAddress((void**)&w2out_p, g_w2out);

    const int GEMM_SMEM = 3 * 32768;
    cudaFuncSetAttribute(gemm_mma, cudaFuncAttributeMaxDynamicSharedMemorySize, GEMM_SMEM);
    cudaFuncSetAttribute(flash_tc, cudaFuncAttributeMaxDynamicSharedMemorySize, 81920);

    // weight + activation split conversions
    conv_wt<<<dim3(NQKV / 32, DMODEL / 32), 128>>>(w_qkv, w2qkv_p, DMODEL, NQKV);
    conv_wt<<<dim3(DMODEL / 32, DMODEL / 32), 128>>>(w_out, w2out_p, DMODEL, DMODEL);
    conv_act<<<(SEQ * DMODEL / 8 + 255) / 256, 256>>>(x, a2_p, SEQ * DMODEL / 8);

    // QKV projection (tensor cores)
    gemm_mma<<<dim3(SEQ / 128, NQKV / 128), 256, GEMM_SMEM>>>(
        a2_p, w2qkv_p, b_qkv, qkv_p, NQKV, K2Q);

    // RMSNorm + RoPE -> fp16 Q'/K'; V transpose -> fp16
    norm_rope<<<SEQ, 256>>>(cosp, sinp, wq, wk);
    conv_vt<<<dim3(SEQ / 32, DMODEL / 32), 256>>>();

    // tensor-core attention (writes split ctx into g_a2)
    flash_tc<<<dim3(SEQ / 64, NHEAD), 128, 81920>>>();

    // output projection (tensor cores)
    gemm_mma<<<dim3(SEQ / 128, DMODEL / 128), 256, GEMM_SMEM>>>(
        a2_p, w2out_p, b_out, out, DMODEL, K2Q);
}

// round 7
// speedup vs baseline: 6.6621x; 1.5147x over previous
#include <cuda_runtime.h>
#include <cuda_fp16.h>
#include <cstdint>
#include <math.h>

#define SEQ    2048
#define DMODEL 5120
#define NHEAD  40
#define HDIM   128
#define NQKV   15360
#define K2Q    10240            // 2 * 5120 expanded K (GEMM2 only)
#define ATT_SCALE 0.08838834764831845f

// ---------------------------------------------------------------------------
// Scratch (device globals — no allocation allowed)
// ---------------------------------------------------------------------------
__device__ __align__(256) float  g_qkv[(size_t)SEQ * NQKV];
__device__ __align__(256) __half g_a1[(size_t)SEQ * DMODEL];       // x hi-only [M,K]
__device__ __align__(256) __half g_w1[(size_t)NQKV * DMODEL];      // w_qkv^T hi [N,K]
__device__ __align__(256) __half g_a2[(size_t)SEQ * K2Q];          // ctx split [M,2K] (hi,lo)
__device__ __align__(256) __half g_w2out[(size_t)DMODEL * K2Q];    // w_out^T [N,2K] (hi,hi)
__device__ __align__(256) __half g_q2[(size_t)NHEAD * SEQ * 256];  // Q [H,S,256] (hi,lo)
__device__ __align__(256) __half g_k2[(size_t)NHEAD * SEQ * 256];  // K [H,S,256] (hi,hi)
__device__ __align__(256) __half g_vt[(size_t)NHEAD * HDIM * SEQ]; // V^T [H,D,S] fp16

// ---------------------------------------------------------------------------
__device__ __forceinline__ uint32_t smem_u32(const void* p) {
    uint32_t a;
    asm("{ .reg .u64 t; cvta.to.shared.u64 t, %1; cvt.u32.u64 %0, t; }" : "=r"(a) : "l"(p));
    return a;
}
#define CP_ASYNC16(dst, src) \
    asm volatile("cp.async.cg.shared.global [%0], [%1], 16;" :: "r"(dst), "l"(src) : "memory")
#define CP_COMMIT()  asm volatile("cp.async.commit_group;" ::: "memory")
#define CP_WAIT1()   asm volatile("cp.async.wait_group 1;" ::: "memory")
#define CP_WAIT0()   asm volatile("cp.async.wait_group 0;" ::: "memory")

#define LDMX4(r0, r1, r2, r3, addr) \
    asm volatile("ldmatrix.sync.aligned.m8n8.x4.shared.b16 {%0,%1,%2,%3}, [%4];" \
        : "=r"(r0), "=r"(r1), "=r"(r2), "=r"(r3) : "r"(addr))

__device__ __forceinline__ void mma16816(float* d, const uint32_t* a, const uint32_t* b) {
    asm volatile(
        "mma.sync.aligned.m16n8k16.row.col.f32.f16.f16.f32 "
        "{%0,%1,%2,%3}, {%4,%5,%6,%7}, {%8,%9}, {%0,%1,%2,%3};"
        : "+f"(d[0]), "+f"(d[1]), "+f"(d[2]), "+f"(d[3])
        : "r"(a[0]), "r"(a[1]), "r"(a[2]), "r"(a[3]), "r"(b[0]), "r"(b[1]));
}

// ---------------------------------------------------------------------------
// conv_act_hi: [M,K] fp32 -> [M,K] fp16 hi
// ---------------------------------------------------------------------------
__global__ __launch_bounds__(256) void conv_act_hi(const float* __restrict__ in,
                                                   __half* __restrict__ out, int n8)
{
    int t = blockIdx.x * 256 + threadIdx.x;
    if (t >= n8) return;
    size_t k = (size_t)t * 8;
    float4 a = *(const float4*)(in + k);
    float4 b = *(const float4*)(in + k + 4);
    __half o[8];
    o[0] = __float2half_rn(a.x); o[1] = __float2half_rn(a.y);
    o[2] = __float2half_rn(a.z); o[3] = __float2half_rn(a.w);
    o[4] = __float2half_rn(b.x); o[5] = __float2half_rn(b.y);
    o[6] = __float2half_rn(b.z); o[7] = __float2half_rn(b.w);
    *(uint4*)(out + k) = *(const uint4*)o;
}

// ---------------------------------------------------------------------------
// conv_wt_hi: [K,N] fp32 -> [N,K] fp16 hi (transpose)
// ---------------------------------------------------------------------------
__global__ __launch_bounds__(128) void conv_wt_hi(const float* __restrict__ W,
                                                  __half* __restrict__ Wt,
                                                  int Kdim, int Ndim)
{
    __shared__ float tile[32][33];
    const int k0 = blockIdx.y * 32, n0 = blockIdx.x * 32;
    const int lane = threadIdx.x & 31, warp = threadIdx.x >> 5;
#pragma unroll
    for (int i = 0; i < 8; i++) {
        int kr = warp + i * 4;
        tile[kr][lane] = W[(size_t)(k0 + kr) * Ndim + n0 + lane];
    }
    __syncthreads();
    const int nl = threadIdx.x >> 2;
    const int ks = threadIdx.x & 3;
    __half o[8];
#pragma unroll
    for (int e = 0; e < 8; e++)
        o[e] = __float2half_rn(tile[ks * 8 + e][nl]);
    *(uint4*)(Wt + (size_t)(n0 + nl) * (size_t)Kdim + k0 + ks * 8) = *(const uint4*)o;
}

// ---------------------------------------------------------------------------
// conv_wt2: [K,N] fp32 -> [N,2K] fp16 pattern (hi, hi)   (GEMM2 weights)
// ---------------------------------------------------------------------------
__global__ __launch_bounds__(128) void conv_wt2(const float* __restrict__ W,
                                                __half* __restrict__ Wt,
                                                int Kdim, int Ndim)
{
    __shared__ float tile[32][33];
    const int k0 = blockIdx.y * 32, n0 = blockIdx.x * 32;
    const int lane = threadIdx.x & 31, warp = threadIdx.x >> 5;
#pragma unroll
    for (int i = 0; i < 8; i++) {
        int kr = warp + i * 4;
        tile[kr][lane] = W[(size_t)(k0 + kr) * Ndim + n0 + lane];
    }
    __syncthreads();
    const int nl = threadIdx.x >> 2;
    const int ks = threadIdx.x & 3;
    __half o[16];
#pragma unroll
    for (int e = 0; e < 8; e++) {
        __half hi = __float2half_rn(tile[ks * 8 + e][nl]);
        o[2 * e] = hi; o[2 * e + 1] = hi;
    }
    uint4* dst = (uint4*)(Wt + (size_t)(n0 + nl) * (2 * (size_t)Kdim) + 2 * (k0 + ks * 8));
    const uint4* src = (const uint4*)o;
    dst[0] = src[0]; dst[1] = src[1];
}

// ---------------------------------------------------------------------------
// conv_vt: V [S, d@qkv] fp32 -> V^T [H, D, S] fp16
// ---------------------------------------------------------------------------
__global__ __launch_bounds__(256) void conv_vt()
{
    __shared__ float t[32][33];
    const int s0  = blockIdx.x * 32;
    const int d0g = blockIdx.y * 32;
    const int h   = d0g >> 7;
    const int dh0 = d0g & 127;
    const int lx = threadIdx.x & 31, ly = threadIdx.x >> 5;
    const float* src = g_qkv + 2 * DMODEL + (size_t)h * HDIM + dh0;
#pragma unroll
    for (int r = 0; r < 4; r++) {
        int srow = ly + r * 8;
        t[srow][lx] = src[(size_t)(s0 + srow) * NQKV + lx];
    }
    __syncthreads();
#pragma unroll
    for (int r = 0; r < 4; r++) {
        int dd = ly + r * 8;
        g_vt[(size_t)(d0g + dd) * SEQ + s0 + lx] = __float2half_rn(t[lx][dd]);
    }
}

// ---------------------------------------------------------------------------
// mma.sync GEMM with ldmatrix fragments: C = A[M,K2] x B[N,K2]^T + bias
// CTA 128x128, BK=64, 3-stage cp.async, 8 warps (4M x 2N), warp 32x64.
// ---------------------------------------------------------------------------
__global__ __launch_bounds__(256, 2) void gemm_mma(
    const __half* __restrict__ A, const __half* __restrict__ B,
    const float* __restrict__ bias, float* __restrict__ C, int N, int K2)
{
    extern __shared__ char smem[];
    const uint32_t sb = smem_u32(smem);
    const int tid = threadIdx.x;
    const int lane = tid & 31;
    const int wid = tid >> 5;
    const int wm = (wid & 3) * 32;
    const int wn = (wid >> 2) * 64;
    const uint32_t SSZ = 32768;

    const size_t arow0 = (size_t)blockIdx.x * 128;
    const size_t brow0 = (size_t)blockIdx.y * 128;
    const int NC = K2 / 64;

    auto load_stage = [&](int st, int kc) {
        const uint32_t ab = sb + st * SSZ;
#pragma unroll
        for (int i = 0; i < 4; i++) {
            int id = tid + i * 256;
            int row = id >> 3, c = id & 7;
            uint32_t dst = ab + (uint32_t)(row * 128) + (((uint32_t)(c ^ (row & 7))) << 4);
            CP_ASYNC16(dst, A + (arow0 + row) * (size_t)K2 + kc * 64 + c * 8);
        }
#pragma unroll
        for (int i = 0; i < 4; i++) {
            int id = tid + i * 256;
            int row = id >> 3, c = id & 7;
            uint32_t dst = ab + 16384u + (uint32_t)(row * 128) + (((uint32_t)(c ^ (row & 7))) << 4);
            CP_ASYNC16(dst, B + (brow0 + row) * (size_t)K2 + kc * 64 + c * 8);
        }
    };

    float acc[2][8][4];
#pragma unroll
    for (int i = 0; i < 2; i++)
#pragma unroll
        for (int j = 0; j < 8; j++)
#pragma unroll
            for (int e = 0; e < 4; e++) acc[i][j][e] = 0.f;

    load_stage(0, 0); CP_COMMIT();
    load_stage(1, 1); CP_COMMIT();

    const int g = lane >> 2;
    const int tig = lane & 3;
    const int lr = lane & 15;
    const uint32_t lc = (uint32_t)(lane >> 4);
    const uint32_t xr = (uint32_t)(lane & 7);
    const uint32_t rowA0 = (uint32_t)((wm + lr) * 128);
    const uint32_t rowA1 = rowA0 + 16 * 128;
    uint32_t rowB[4];
#pragma unroll
    for (int jj = 0; jj < 4; jj++)
        rowB[jj] = 16384u + (uint32_t)((wn + 16 * jj + lr) * 128);

    for (int cc = 0; cc < NC; cc++) {
        CP_WAIT1();
        __syncthreads();
        if (cc + 2 < NC) load_stage((cc + 2) % 3, cc + 2);
        CP_COMMIT();

        const uint32_t sA = sb + (cc % 3) * SSZ;
#pragma unroll
        for (int ks = 0; ks < 4; ks++) {
            const uint32_t xcol = ((((uint32_t)(2 * ks) + lc) ^ xr) << 4);
            uint32_t a[2][4], b[8][2];
            LDMX4(a[0][0], a[0][1], a[0][2], a[0][3], sA + rowA0 + xcol);
            LDMX4(a[1][0], a[1][1], a[1][2], a[1][3], sA + rowA1 + xcol);
#pragma unroll
            for (int jj = 0; jj < 4; jj++)
                LDMX4(b[2 * jj][0], b[2 * jj + 1][0], b[2 * jj][1], b[2 * jj + 1][1],
                      sA + rowB[jj] + xcol);
#pragma unroll
            for (int i = 0; i < 2; i++)
#pragma unroll
                for (int j = 0; j < 8; j++)
                    mma16816(acc[i][j], a[i], b[j]);
        }
        __syncthreads();
    }

#pragma unroll
    for (int i = 0; i < 2; i++) {
        int r = (int)arow0 + wm + i * 16 + g;
#pragma unroll
        for (int j = 0; j < 8; j++) {
            int c = (int)brow0 + wn + j * 8 + tig * 2;
            float bx = bias[c], by = bias[c + 1];
            float2 v0 = {acc[i][j][0] + bx, acc[i][j][1] + by};
            float2 v1 = {acc[i][j][2] + bx, acc[i][j][3] + by};
            *(float2*)(C + (size_t)r * N + c) = v0;
            *(float2*)(C + (size_t)(r + 8) * N + c) = v1;
        }
    }
}

// ---------------------------------------------------------------------------
// RMSNorm + RoPE -> fp16 Q' (hi,lo) and K' (hi,hi), layout [H,S,256]
// ---------------------------------------------------------------------------
__global__ __launch_bounds__(256) void norm_rope(
    const float* __restrict__ cosp, const float* __restrict__ sinp,
    const float* __restrict__ wq, const float* __restrict__ wk)
{
    const int s = blockIdx.x;
    const int tid = threadIdx.x;
    const float* qrow = g_qkv + (size_t)s * NQKV;
    const float* krow = qrow + DMODEL;

    float sq = 0.f, sk = 0.f;
    for (int i = tid; i < DMODEL; i += 256) {
        float a = qrow[i]; sq += a * a;
        float b = krow[i]; sk += b * b;
    }
#pragma unroll
    for (int off = 16; off; off >>= 1) {
        sq += __shfl_xor_sync(0xffffffffu, sq, off);
        sk += __shfl_xor_sync(0xffffffffu, sk, off);
    }
    __shared__ float shq[8], shk[8];
    if ((tid & 31) == 0) { shq[tid >> 5] = sq; shk[tid >> 5] = sk; }
    __syncthreads();
    float tq = 0.f, tk = 0.f;
#pragma unroll
    for (int i = 0; i < 8; i++) { tq += shq[i]; tk += shk[i]; }
    const float rq = rsqrtf(tq / DMODEL + 1e-6f);
    const float rk = rsqrtf(tk / DMODEL + 1e-6f);

    for (int p = tid; p < DMODEL / 2; p += 256) {
        const int i0 = 2 * p;
        const int h = i0 >> 7;
        const int dl = i0 & 127;
        const float c  = cosp[s * HDIM + dl];
        const float sn = sinp[s * HDIM + dl];
        float q0 = qrow[i0] * rq * wq[i0];
        float q1 = qrow[i0 + 1] * rq * wq[i0 + 1];
        float k0 = krow[i0] * rk * wk[i0];
        float k1 = krow[i0 + 1] * rk * wk[i0 + 1];
        float qe = q0 * c - q1 * sn;
        float qo = q0 * sn + q1 * c;
        float ke = k0 * c - k1 * sn;
        float ko = k0 * sn + k1 * c;

        const size_t base = ((size_t)h * SEQ + s) * 256 + 2 * dl;
        __half qeh = __float2half_rn(qe);
        __half qel = __float2half_rn(qe - __half2float(qeh));
        __half qoh = __float2half_rn(qo);
        __half qol = __float2half_rn(qo - __half2float(qoh));
        __half qv[4] = {qeh, qel, qoh, qol};
        *(uint2*)(g_q2 + base) = *(const uint2*)qv;

        __half keh = __float2half_rn(ke);
        __half koh = __float2half_rn(ko);
        __half kv[4] = {keh, keh, koh, koh};
        *(uint2*)(g_k2 + base) = *(const uint2*)kv;
    }
}

// ---------------------------------------------------------------------------
// Tensor-core flash attention (ldmatrix fragments). CTA: 64 q x 1 head.
// smem: Q' 32KB @0, K' 32KB @32768, Vt 16KB @65536. Total 81920.
// ---------------------------------------------------------------------------
__global__ __launch_bounds__(128, 2) void flash_tc()
{
    extern __shared__ char smem[];
    const uint32_t sb = smem_u32(smem);
    const int h  = blockIdx.y;
    const int qt = blockIdx.x;
    const int tid = threadIdx.x;
    const int lane = tid & 31;
    const int wid = tid >> 5;
    const int g = lane >> 2;
    const int tig = lane & 3;
    const int lr = lane & 15;
    const uint32_t lc = (uint32_t)(lane >> 4);
    const uint32_t xr = (uint32_t)(lane & 7);

    const __half* Qg = g_q2 + ((size_t)h * SEQ + qt * 64) * 256;
    const __half* Kg = g_k2 + (size_t)h * SEQ * 256;
    const __half* Vg = g_vt + (size_t)h * HDIM * SEQ;

    // load Q' once
#pragma unroll
    for (int i = 0; i < 16; i++) {
        int id = tid + i * 128;
        int r = id >> 5, c = id & 31;
        uint32_t dst = sb + (uint32_t)(r * 512) + (((uint32_t)(c ^ (r & 7))) << 4);
        CP_ASYNC16(dst, Qg + (size_t)r * 256 + c * 8);
    }
    CP_COMMIT();

    const uint32_t rowQ = (uint32_t)((wid * 16 + lr) * 512);
    uint32_t rowK[4], rowV[8];
#pragma unroll
    for (int jj = 0; jj < 4; jj++)
        rowK[jj] = 32768u + (uint32_t)((16 * jj + lr) * 512);
#pragma unroll
    for (int jj = 0; jj < 8; jj++)
        rowV[jj] = 65536u + (uint32_t)((16 * jj + lr) * 128);

    float o[16][4];
#pragma unroll
    for (int jd = 0; jd < 16; jd++)
#pragma unroll
        for (int e = 0; e < 4; e++) o[jd][e] = 0.f;
    float mA = -1e30f, mB = -1e30f, lA = 0.f, lB = 0.f;

    for (int kt = 0; kt < SEQ / 64; kt++) {
        __syncthreads();
#pragma unroll
        for (int i = 0; i < 16; i++) {
            int id = tid + i * 128;
            int r = id >> 5, c = id & 31;
            uint32_t dst = sb + 32768u + (uint32_t)(r * 512) + (((uint32_t)(c ^ (r & 7))) << 4);
            CP_ASYNC16(dst, Kg + (size_t)(kt * 64 + r) * 256 + c * 8);
        }
#pragma unroll
        for (int i = 0; i < 8; i++) {
            int id = tid + i * 128;
            int r = id >> 3, c = id & 7;
            uint32_t dst = sb + 65536u + (uint32_t)(r * 128) + (((uint32_t)(c ^ (r & 7))) << 4);
            CP_ASYNC16(dst, Vg + (size_t)r * SEQ + kt * 64 + c * 8);
        }
        CP_COMMIT();
        CP_WAIT0();
        __syncthreads();

        // ---- S = Q' K'^T (k-dim 256) ----
        float sacc[8][4];
#pragma unroll
        for (int j = 0; j < 8; j++)
#pragma unroll
            for (int e = 0; e < 4; e++) sacc[j][e] = 0.f;

#pragma unroll
        for (int ks = 0; ks < 16; ks++) {
            const uint32_t xcol = ((((uint32_t)(2 * ks) + lc) ^ xr) << 4);
            uint32_t a[4], b[8][2];
            LDMX4(a[0], a[1], a[2], a[3], sb + rowQ + xcol);
#pragma unroll
            for (int jj = 0; jj < 4; jj++)
                LDMX4(b[2 * jj][0], b[2 * jj + 1][0], b[2 * jj][1], b[2 * jj + 1][1],
                      sb + rowK[jj] + xcol);
#pragma unroll
            for (int j = 0; j < 8; j++)
                mma16816(sacc[j], a, b[j]);
        }

        // ---- online softmax ----
        float mxA = -1e30f, mxB = -1e30f;
#pragma unroll
        for (int j = 0; j < 8; j++) {
            sacc[j][0] *= ATT_SCALE; sacc[j][1] *= ATT_SCALE;
            sacc[j][2] *= ATT_SCALE; sacc[j][3] *= ATT_SCALE;
            mxA = fmaxf(mxA, fmaxf(sacc[j][0], sacc[j][1]));
            mxB = fmaxf(mxB, fmaxf(sacc[j][2], sacc[j][3]));
        }
        mxA = fmaxf(mxA, __shfl_xor_sync(0xffffffffu, mxA, 1));
        mxA = fmaxf(mxA, __shfl_xor_sync(0xffffffffu, mxA, 2));
        mxB = fmaxf(mxB, __shfl_xor_sync(0xffffffffu, mxB, 1));
        mxB = fmaxf(mxB, __shfl_xor_sync(0xffffffffu, mxB, 2));
        const float mnA = fmaxf(mA, mxA);
        const float mnB = fmaxf(mB, mxB);
        const float fsA = __expf(mA - mnA);
        const float fsB = __expf(mB - mnB);
        float psA = 0.f, psB = 0.f;
        uint32_t pA[8], pB[8];
#pragma unroll
        for (int j = 0; j < 8; j++) {
            float p0 = __expf(sacc[j][0] - mnA);
            float p1 = __expf(sacc[j][1] - mnA);
            float p2 = __expf(sacc[j][2] - mnB);
            float p3 = __expf(sacc[j][3] - mnB);
            psA += p0 + p1; psB += p2 + p3;
            __half2 hA = __floats2half2_rn(p0, p1);
            __half2 hB = __floats2half2_rn(p2, p3);
            pA[j] = *(uint32_t*)&hA;
            pB[j] = *(uint32_t*)&hB;
        }
        psA += __shfl_xor_sync(0xffffffffu, psA, 1);
        psA += __shfl_xor_sync(0xffffffffu, psA, 2);
        psB += __shfl_xor_sync(0xffffffffu, psB, 1);
        psB += __shfl_xor_sync(0xffffffffu, psB, 2);
        lA = lA * fsA + psA;
        lB = lB * fsB + psB;
        mA = mnA; mB = mnB;
#pragma unroll
        for (int jd = 0; jd < 16; jd++) {
            o[jd][0] *= fsA; o[jd][1] *= fsA;
            o[jd][2] *= fsB; o[jd][3] *= fsB;
        }

        // ---- O += P V^T ----
#pragma unroll
        for (int kk = 0; kk < 4; kk++) {
            uint32_t a2[4] = {pA[2 * kk], pB[2 * kk], pA[2 * kk + 1], pB[2 * kk + 1]};
            const uint32_t xcol = ((((uint32_t)(2 * kk) + lc) ^ xr) << 4);
            uint32_t bv[16][2];
#pragma unroll
            for (int jj = 0; jj < 8; jj++)
                LDMX4(bv[2 * jj][0], bv[2 * jj + 1][0], bv[2 * jj][1], bv[2 * jj + 1][1],
                      sb + rowV[jj] + xcol);
#pragma unroll
            for (int jd = 0; jd < 16; jd++)
                mma16816(o[jd], a2, bv[jd]);
        }
    }

    // ---- epilogue: split (hi,lo) into g_a2 [S, 2*DMODEL] ----
    const float invA = 1.0f / lA;
    const float invB = 1.0f / lB;
    const int rA = qt * 64 + wid * 16 + g;
    const int rB = rA + 8;
#pragma unroll
    for (int jd = 0; jd < 16; jd++) {
        const int c = 8 * jd + 2 * tig;
        const size_t colh = 2 * ((size_t)h * HDIM + c);
        float vA0 = o[jd][0] * invA, vA1 = o[jd][1] * invA;
        float vB0 = o[jd][2] * invB, vB1 = o[jd][3] * invB;
        __half wa[4], wb[4];
        wa[0] = __float2half_rn(vA0); wa[1] = __float2half_rn(vA0 - __half2float(wa[0]));
        wa[2] = __float2half_rn(vA1); wa[3] = __float2half_rn(vA1 - __half2float(wa[2]));
        wb[0] = __float2half_rn(vB0); wb[1] = __float2half_rn(vB0 - __half2float(wb[0]));
        wb[2] = __float2half_rn(vB1); wb[3] = __float2half_rn(vB1 - __half2float(wb[2]));
        *(uint2*)(g_a2 + (size_t)rA * K2Q + colh) = *(const uint2*)wa;
        *(uint2*)(g_a2 + (size_t)rB * K2Q + colh) = *(const uint2*)wb;
    }
}

// ---------------------------------------------------------------------------
extern "C" void kernel_launch(void* const* d_in, const int* in_sizes, int n_in,
                              void* d_out, int out_size)
{
    const float* x     = (const float*)d_in[0];
    const float* cosp  = (const float*)d_in[1];
    const float* sinp  = (const float*)d_in[2];
    const float* w_qkv = (const float*)d_in[3];
    const float* b_qkv = (const float*)d_in[4];
    const float* wq    = (const float*)d_in[5];
    const float* wk    = (const float*)d_in[6];
    const float* w_out = (const float*)d_in[7];
    const float* b_out = (const float*)d_in[8];
    float* out = (float*)d_out;

    float* qkv_p;
    __half *a1_p, *w1_p, *a2_p, *w2out_p;
    cudaGetSymbolAddress((void**)&qkv_p,   g_qkv);
    cudaGetSymbolAddress((void**)&a1_p,    g_a1);
    cudaGetSymbolAddress((void**)&w1_p,    g_w1);
    cudaGetSymbolAddress((void**)&a2_p,    g_a2);
    cudaGetSymbolAddress((void**)&w2out_p, g_w2out);

    const int GEMM_SMEM = 3 * 32768;
    cudaFuncSetAttribute(gemm_mma, cudaFuncAttributeMaxDynamicSharedMemorySize, GEMM_SMEM);
    cudaFuncSetAttribute(flash_tc, cudaFuncAttributeMaxDynamicSharedMemorySize, 81920);

    // conversions
    conv_wt_hi<<<dim3(NQKV / 32, DMODEL / 32), 128>>>(w_qkv, w1_p, DMODEL, NQKV);
    conv_wt2<<<dim3(DMODEL / 32, DMODEL / 32), 128>>>(w_out, w2out_p, DMODEL, DMODEL);
    conv_act_hi<<<(SEQ * DMODEL / 8 + 255) / 256, 256>>>(x, a1_p, SEQ * DMODEL / 8);

    // QKV projection: hi-only, K=5120
    gemm_mma<<<dim3(SEQ / 128, NQKV / 128), 256, GEMM_SMEM>>>(
        a1_p, w1_p, b_qkv, qkv_p, NQKV, DMODEL);

    // RMSNorm + RoPE; V transpose
    norm_rope<<<SEQ, 256>>>(cosp, sinp, wq, wk);
    conv_vt<<<dim3(SEQ / 32, DMODEL / 32), 256>>>();

    // tensor-core attention (writes split ctx into g_a2)
    flash_tc<<<dim3(SEQ / 64, NHEAD), 128, 81920>>>();

    // output projection: split acts, K2=10240
    gemm_mma<<<dim3(SEQ / 128, DMODEL / 128), 256, GEMM_SMEM>>>(
        a2_p, w2out_p, b_out, out, DMODEL, K2Q);
}

// round 9
// speedup vs baseline: 8.0312x; 1.2055x over previous
#include <cuda_runtime.h>
#include <cuda_fp16.h>
#include <cstdint>
#include <math.h>

#define SEQ    2048
#define DMODEL 5120
#define NHEAD  40
#define HDIM   128
#define NQKV   15360
#define ATT_SCALE 0.08838834764831845f

// ---------------------------------------------------------------------------
// Scratch (device globals — no allocation allowed)
// ---------------------------------------------------------------------------
__device__ __align__(256) float  g_qkv[(size_t)SEQ * NQKV];
__device__ __align__(256) __half g_a1[(size_t)SEQ * DMODEL];        // act hi [M,K]; reused for x and ctx
__device__ __align__(256) __half g_w1[(size_t)NQKV * DMODEL];       // w_qkv^T hi [N,K]
__device__ __align__(256) __half g_w2[(size_t)DMODEL * DMODEL];     // w_out^T hi [N,K]
__device__ __align__(256) __half g_q2[(size_t)NHEAD * SEQ * 256];   // Q [H,S,256] (hi,lo)
__device__ __align__(256) __half g_k2[(size_t)NHEAD * SEQ * 256];   // K [H,S,256] (hi,hi)
__device__ __align__(256) __half g_vt[(size_t)NHEAD * HDIM * SEQ];  // V^T [H,D,S] fp16

// ---------------------------------------------------------------------------
__device__ __forceinline__ uint32_t smem_u32(const void* p) {
    uint32_t a;
    asm("{ .reg .u64 t; cvta.to.shared.u64 t, %1; cvt.u32.u64 %0, t; }" : "=r"(a) : "l"(p));
    return a;
}
#define CP_ASYNC16(dst, src) \
    asm volatile("cp.async.cg.shared.global [%0], [%1], 16;" :: "r"(dst), "l"(src) : "memory")
#define CP_COMMIT()  asm volatile("cp.async.commit_group;" ::: "memory")
#define CP_WAIT1()   asm volatile("cp.async.wait_group 1;" ::: "memory")
#define CP_WAIT0()   asm volatile("cp.async.wait_group 0;" ::: "memory")

#define LDMX4(r0, r1, r2, r3, addr) \
    asm volatile("ldmatrix.sync.aligned.m8n8.x4.shared.b16 {%0,%1,%2,%3}, [%4];" \
        : "=r"(r0), "=r"(r1), "=r"(r2), "=r"(r3) : "r"(addr))

__device__ __forceinline__ void mma16816(float* d, const uint32_t* a, const uint32_t* b) {
    asm volatile(
        "mma.sync.aligned.m16n8k16.row.col.f32.f16.f16.f32 "
        "{%0,%1,%2,%3}, {%4,%5,%6,%7}, {%8,%9}, {%0,%1,%2,%3};"
        : "+f"(d[0]), "+f"(d[1]), "+f"(d[2]), "+f"(d[3])
        : "r"(a[0]), "r"(a[1]), "r"(a[2]), "r"(a[3]), "r"(b[0]), "r"(b[1]));
}

// ---------------------------------------------------------------------------
// conv_act_hi: [M,K] fp32 -> [M,K] fp16 hi
// ---------------------------------------------------------------------------
__global__ __launch_bounds__(256) void conv_act_hi(const float* __restrict__ in,
                                                   __half* __restrict__ out, int n8)
{
    int t = blockIdx.x * 256 + threadIdx.x;
    if (t >= n8) return;
    size_t k = (size_t)t * 8;
    float4 a = *(const float4*)(in + k);
    float4 b = *(const float4*)(in + k + 4);
    __half o[8];
    o[0] = __float2half_rn(a.x); o[1] = __float2half_rn(a.y);
    o[2] = __float2half_rn(a.z); o[3] = __float2half_rn(a.w);
    o[4] = __float2half_rn(b.x); o[5] = __float2half_rn(b.y);
    o[6] = __float2half_rn(b.z); o[7] = __float2half_rn(b.w);
    *(uint4*)(out + k) = *(const uint4*)o;
}

// ---------------------------------------------------------------------------
// conv_wt_hi: [K,N] fp32 -> [N,K] fp16 hi (transpose)
// ---------------------------------------------------------------------------
__global__ __launch_bounds__(128) void conv_wt_hi(const float* __restrict__ W,
                                                  __half* __restrict__ Wt,
                                                  int Kdim, int Ndim)
{
    __shared__ float tile[32][33];
    const int k0 = blockIdx.y * 32, n0 = blockIdx.x * 32;
    const int lane = threadIdx.x & 31, warp = threadIdx.x >> 5;
#pragma unroll
    for (int i = 0; i < 8; i++) {
        int kr = warp + i * 4;
        tile[kr][lane] = W[(size_t)(k0 + kr) * Ndim + n0 + lane];
    }
    __syncthreads();
    const int nl = threadIdx.x >> 2;
    const int ks = threadIdx.x & 3;
    __half o[8];
#pragma unroll
    for (int e = 0; e < 8; e++)
        o[e] = __float2half_rn(tile[ks * 8 + e][nl]);
    *(uint4*)(Wt + (size_t)(n0 + nl) * (size_t)Kdim + k0 + ks * 8) = *(const uint4*)o;
}

// ---------------------------------------------------------------------------
// conv_vt: V [S, d@qkv] fp32 -> V^T [H, D, S] fp16
// ---------------------------------------------------------------------------
__global__ __launch_bounds__(256) void conv_vt()
{
    __shared__ float t[32][33];
    const int s0  = blockIdx.x * 32;
    const int d0g = blockIdx.y * 32;
    const int h   = d0g >> 7;
    const int dh0 = d0g & 127;
    const int lx = threadIdx.x & 31, ly = threadIdx.x >> 5;
    const float* src = g_qkv + 2 * DMODEL + (size_t)h * HDIM + dh0;
#pragma unroll
    for (int r = 0; r < 4; r++) {
        int srow = ly + r * 8;
        t[srow][lx] = src[(size_t)(s0 + srow) * NQKV + lx];
    }
    __syncthreads();
#pragma unroll
    for (int r = 0; r < 4; r++) {
        int dd = ly + r * 8;
        g_vt[(size_t)(d0g + dd) * SEQ + s0 + lx] = __float2half_rn(t[lx][dd]);
    }
}

// ---------------------------------------------------------------------------
// mma.sync GEMM with ldmatrix: C = A[M,K2] x B[N,K2]^T + bias
// CTA 128x128, BK=64, 3-stage cp.async, 8 warps (4M x 2N), warp 32x64.
// All loop-invariant addressing precomputed (alu diet).
// ---------------------------------------------------------------------------
__global__ __launch_bounds__(256, 2) void gemm_mma(
    const __half* __restrict__ A, const __half* __restrict__ B,
    const float* __restrict__ bias, float* __restrict__ C, int N, int K2)
{
    extern __shared__ char smem[];
    const uint32_t sb = smem_u32(smem);
    const int tid = threadIdx.x;
    const int lane = tid & 31;
    const int wid = tid >> 5;
    const int wm = (wid & 3) * 32;
    const int wn = (wid >> 2) * 64;
    const uint32_t SSZ = 32768;

    const size_t arow0 = (size_t)blockIdx.x * 128;
    const size_t brow0 = (size_t)blockIdx.y * 128;
    const int NC = K2 / 64;

    // --- precomputed cp.async addressing ---
    const int row0 = tid >> 3, c0 = tid & 7;
    const uint32_t offA0 = (uint32_t)(row0 * 128) + (((uint32_t)(c0 ^ (row0 & 7))) << 4);
    const __half* srcA0 = A + (arow0 + row0) * (size_t)K2 + c0 * 8;
    const __half* srcB0 = B + (brow0 + row0) * (size_t)K2 + c0 * 8;
    const size_t rstep = (size_t)32 * K2;

    auto load_stage = [&](uint32_t stbase, int kc) {
        const __half* sa = srcA0 + kc * 64;
        const __half* sbp = srcB0 + kc * 64;
#pragma unroll
        for (int i = 0; i < 4; i++)
            CP_ASYNC16(stbase + offA0 + (uint32_t)i * 4096u, sa + rstep * i);
#pragma unroll
        for (int i = 0; i < 4; i++)
            CP_ASYNC16(stbase + 16384u + offA0 + (uint32_t)i * 4096u, sbp + rstep * i);
    };

    float acc[2][8][4];
#pragma unroll
    for (int i = 0; i < 2; i++)
#pragma unroll
        for (int j = 0; j < 8; j++)
#pragma unroll
            for (int e = 0; e < 4; e++) acc[i][j][e] = 0.f;

    load_stage(sb, 0); CP_COMMIT();
    load_stage(sb + SSZ, 1); CP_COMMIT();

    const int g = lane >> 2;
    const int tig = lane & 3;
    const int lr = lane & 15;
    const uint32_t lc = (uint32_t)(lane >> 4);
    const uint32_t xr = (uint32_t)(lane & 7);
    // fragment row bases + per-k-step swizzled columns (loop invariant)
    const uint32_t rowA0 = (uint32_t)((wm + lr) * 128);
    const uint32_t rowA1 = rowA0 + 16 * 128;
    uint32_t rowB[4];
#pragma unroll
    for (int jj = 0; jj < 4; jj++)
        rowB[jj] = 16384u + (uint32_t)((wn + 16 * jj + lr) * 128);
    uint32_t xcol[4];
#pragma unroll
    for (int ks = 0; ks < 4; ks++)
        xcol[ks] = ((((uint32_t)(2 * ks) + lc) ^ xr) << 4);

    uint32_t curst = 0, pfst = 2;   // rotating stage indices

    for (int cc = 0; cc < NC; cc++) {
        CP_WAIT1();
        __syncthreads();
        if (cc + 2 < NC) load_stage(sb + pfst * SSZ, cc + 2);
        CP_COMMIT();

        const uint32_t sA = sb + curst * SSZ;
#pragma unroll
        for (int ks = 0; ks < 4; ks++) {
            const uint32_t xc = xcol[ks];
            uint32_t a[2][4], b[8][2];
            LDMX4(a[0][0], a[0][1], a[0][2], a[0][3], sA + rowA0 + xc);
            LDMX4(a[1][0], a[1][1], a[1][2], a[1][3], sA + rowA1 + xc);
#pragma unroll
            for (int jj = 0; jj < 4; jj++)
                LDMX4(b[2 * jj][0], b[2 * jj + 1][0], b[2 * jj][1], b[2 * jj + 1][1],
                      sA + rowB[jj] + xc);
#pragma unroll
            for (int i = 0; i < 2; i++)
#pragma unroll
                for (int j = 0; j < 8; j++)
                    mma16816(acc[i][j], a[i], b[j]);
        }
        __syncthreads();
        curst = (curst == 2) ? 0 : curst + 1;
        pfst  = (pfst == 2) ? 0 : pfst + 1;
    }

#pragma unroll
    for (int i = 0; i < 2; i++) {
        int r = (int)arow0 + wm + i * 16 + g;
#pragma unroll
        for (int j = 0; j < 8; j++) {
            int c = (int)brow0 + wn + j * 8 + tig * 2;
            float bx = bias[c], by = bias[c + 1];
            float2 v0 = {acc[i][j][0] + bx, acc[i][j][1] + by};
            float2 v1 = {acc[i][j][2] + bx, acc[i][j][3] + by};
            *(float2*)(C + (size_t)r * N + c) = v0;
            *(float2*)(C + (size_t)(r + 8) * N + c) = v1;
        }
    }
}

// ---------------------------------------------------------------------------
// RMSNorm + RoPE -> fp16 Q' (hi,lo) and K' (hi,hi), layout [H,S,256]
// ---------------------------------------------------------------------------
__global__ __launch_bounds__(256) void norm_rope(
    const float* __restrict__ cosp, const float* __restrict__ sinp,
    const float* __restrict__ wq, const float* __restrict__ wk)
{
    const int s = blockIdx.x;
    const int tid = threadIdx.x;
    const float* qrow = g_qkv + (size_t)s * NQKV;
    const float* krow = qrow + DMODEL;

    float sq = 0.f, sk = 0.f;
    for (int i = tid; i < DMODEL; i += 256) {
        float a = qrow[i]; sq += a * a;
        float b = krow[i]; sk += b * b;
    }
#pragma unroll
    for (int off = 16; off; off >>= 1) {
        sq += __shfl_xor_sync(0xffffffffu, sq, off);
        sk += __shfl_xor_sync(0xffffffffu, sk, off);
    }
    __shared__ float shq[8], shk[8];
    if ((tid & 31) == 0) { shq[tid >> 5] = sq; shk[tid >> 5] = sk; }
    __syncthreads();
    float tq = 0.f, tk = 0.f;
#pragma unroll
    for (int i = 0; i < 8; i++) { tq += shq[i]; tk += shk[i]; }
    const float rq = rsqrtf(tq / DMODEL + 1e-6f);
    const float rk = rsqrtf(tk / DMODEL + 1e-6f);

    for (int p = tid; p < DMODEL / 2; p += 256) {
        const int i0 = 2 * p;
        const int h = i0 >> 7;
        const int dl = i0 & 127;
        const float c  = cosp[s * HDIM + dl];
        const float sn = sinp[s * HDIM + dl];
        float q0 = qrow[i0] * rq * wq[i0];
        float q1 = qrow[i0 + 1] * rq * wq[i0 + 1];
        float k0 = krow[i0] * rk * wk[i0];
        float k1 = krow[i0 + 1] * rk * wk[i0 + 1];
        float qe = q0 * c - q1 * sn;
        float qo = q0 * sn + q1 * c;
        float ke = k0 * c - k1 * sn;
        float ko = k0 * sn + k1 * c;

        const size_t base = ((size_t)h * SEQ + s) * 256 + 2 * dl;
        __half qeh = __float2half_rn(qe);
        __half qel = __float2half_rn(qe - __half2float(qeh));
        __half qoh = __float2half_rn(qo);
        __half qol = __float2half_rn(qo - __half2float(qoh));
        __half qv[4] = {qeh, qel, qoh, qol};
        *(uint2*)(g_q2 + base) = *(const uint2*)qv;

        __half keh = __float2half_rn(ke);
        __half koh = __float2half_rn(ko);
        __half kv[4] = {keh, keh, koh, koh};
        *(uint2*)(g_k2 + base) = *(const uint2*)kv;
    }
}

// ---------------------------------------------------------------------------
// Tensor-core flash attention (ldmatrix). CTA: 64 q x 1 head, 4 warps.
// smem: Q' 32KB @0, K' 32KB @32768, Vt 16KB @65536. Total 81920.
// Epilogue: ctx hi-only fp16 into g_a1 [S, DMODEL].
// ---------------------------------------------------------------------------
__global__ __launch_bounds__(128, 2) void flash_tc()
{
    extern __shared__ char smem[];
    const uint32_t sb = smem_u32(smem);
    const int h  = blockIdx.y;
    const int qt = blockIdx.x;
    const int tid = threadIdx.x;
    const int lane = tid & 31;
    const int wid = tid >> 5;
    const int g = lane >> 2;
    const int tig = lane & 3;
    const int lr = lane & 15;
    const uint32_t lc = (uint32_t)(lane >> 4);
    const uint32_t xr = (uint32_t)(lane & 7);

    const __half* Qg = g_q2 + ((size_t)h * SEQ + qt * 64) * 256;
    const __half* Kg = g_k2 + (size_t)h * SEQ * 256;
    const __half* Vg = g_vt + (size_t)h * HDIM * SEQ;

    // load Q' once
#pragma unroll
    for (int i = 0; i < 16; i++) {
        int id = tid + i * 128;
        int r = id >> 5, c = id & 31;
        uint32_t dst = sb + (uint32_t)(r * 512) + (((uint32_t)(c ^ (r & 7))) << 4);
        CP_ASYNC16(dst, Qg + (size_t)r * 256 + c * 8);
    }
    CP_COMMIT();

    const uint32_t rowQ = (uint32_t)((wid * 16 + lr) * 512);
    uint32_t rowK[4], rowV[8];
#pragma unroll
    for (int jj = 0; jj < 4; jj++)
        rowK[jj] = 32768u + (uint32_t)((16 * jj + lr) * 512);
#pragma unroll
    for (int jj = 0; jj < 8; jj++)
        rowV[jj] = 65536u + (uint32_t)((16 * jj + lr) * 128);
    uint32_t xcol[4];
#pragma unroll
    for (int kk = 0; kk < 4; kk++)
        xcol[kk] = ((((uint32_t)(2 * kk) + lc) ^ xr) << 4);

    float o[16][4];
#pragma unroll
    for (int jd = 0; jd < 16; jd++)
#pragma unroll
        for (int e = 0; e < 4; e++) o[jd][e] = 0.f;
    float mA = -1e30f, mB = -1e30f, lA = 0.f, lB = 0.f;

    for (int kt = 0; kt < SEQ / 64; kt++) {
        __syncthreads();
#pragma unroll
        for (int i = 0; i < 16; i++) {
            int id = tid + i * 128;
            int r = id >> 5, c = id & 31;
            uint32_t dst = sb + 32768u + (uint32_t)(r * 512) + (((uint32_t)(c ^ (r & 7))) << 4);
            CP_ASYNC16(dst, Kg + (size_t)(kt * 64 + r) * 256 + c * 8);
        }
#pragma unroll
        for (int i = 0; i < 8; i++) {
            int id = tid + i * 128;
            int r = id >> 3, c = id & 7;
            uint32_t dst = sb + 65536u + (uint32_t)(r * 128) + (((uint32_t)(c ^ (r & 7))) << 4);
            CP_ASYNC16(dst, Vg + (size_t)r * SEQ + kt * 64 + c * 8);
        }
        CP_COMMIT();
        CP_WAIT0();
        __syncthreads();

        // ---- S = Q' K'^T (k-dim 256) ----
        float sacc[8][4];
#pragma unroll
        for (int j = 0; j < 8; j++)
#pragma unroll
            for (int e = 0; e < 4; e++) sacc[j][e] = 0.f;

#pragma unroll
        for (int ks = 0; ks < 16; ks++) {
            const uint32_t xc = ((((uint32_t)(2 * ks) + lc) ^ xr) << 4);
            uint32_t a[4], b[8][2];
            LDMX4(a[0], a[1], a[2], a[3], sb + rowQ + xc);
#pragma unroll
            for (int jj = 0; jj < 4; jj++)
                LDMX4(b[2 * jj][0], b[2 * jj + 1][0], b[2 * jj][1], b[2 * jj + 1][1],
                      sb + rowK[jj] + xc);
#pragma unroll
            for (int j = 0; j < 8; j++)
                mma16816(sacc[j], a, b[j]);
        }

        // ---- online softmax ----
        float mxA = -1e30f, mxB = -1e30f;
#pragma unroll
        for (int j = 0; j < 8; j++) {
            sacc[j][0] *= ATT_SCALE; sacc[j][1] *= ATT_SCALE;
            sacc[j][2] *= ATT_SCALE; sacc[j][3] *= ATT_SCALE;
            mxA = fmaxf(mxA, fmaxf(sacc[j][0], sacc[j][1]));
            mxB = fmaxf(mxB, fmaxf(sacc[j][2], sacc[j][3]));
        }
        mxA = fmaxf(mxA, __shfl_xor_sync(0xffffffffu, mxA, 1));
        mxA = fmaxf(mxA, __shfl_xor_sync(0xffffffffu, mxA, 2));
        mxB = fmaxf(mxB, __shfl_xor_sync(0xffffffffu, mxB, 1));
        mxB = fmaxf(mxB, __shfl_xor_sync(0xffffffffu, mxB, 2));
        const float mnA = fmaxf(mA, mxA);
        const float mnB = fmaxf(mB, mxB);
        const float fsA = __expf(mA - mnA);
        const float fsB = __expf(mB - mnB);
        float psA = 0.f, psB = 0.f;
        uint32_t pA[8], pB[8];
#pragma unroll
        for (int j = 0; j < 8; j++) {
            float p0 = __expf(sacc[j][0] - mnA);
            float p1 = __expf(sacc[j][1] - mnA);
            float p2 = __expf(sacc[j][2] - mnB);
            float p3 = __expf(sacc[j][3] - mnB);
            psA += p0 + p1; psB += p2 + p3;
            __half2 hA = __floats2half2_rn(p0, p1);
            __half2 hB = __floats2half2_rn(p2, p3);
            pA[j] = *(uint32_t*)&hA;
            pB[j] = *(uint32_t*)&hB;
        }
        psA += __shfl_xor_sync(0xffffffffu, psA, 1);
        psA += __shfl_xor_sync(0xffffffffu, psA, 2);
        psB += __shfl_xor_sync(0xffffffffu, psB, 1);
        psB += __shfl_xor_sync(0xffffffffu, psB, 2);
        lA = lA * fsA + psA;
        lB = lB * fsB + psB;
        mA = mnA; mB = mnB;
#pragma unroll
        for (int jd = 0; jd < 16; jd++) {
            o[jd][0] *= fsA; o[jd][1] *= fsA;
            o[jd][2] *= fsB; o[jd][3] *= fsB;
        }

        // ---- O += P V^T ----
#pragma unroll
        for (int kk = 0; kk < 4; kk++) {
            uint32_t a2[4] = {pA[2 * kk], pB[2 * kk], pA[2 * kk + 1], pB[2 * kk + 1]};
            const uint32_t xc = xcol[kk];
            uint32_t bv[16][2];
#pragma unroll
            for (int jj = 0; jj < 8; jj++)
                LDMX4(bv[2 * jj][0], bv[2 * jj + 1][0], bv[2 * jj][1], bv[2 * jj + 1][1],
                      sb + rowV[jj] + xc);
#pragma unroll
            for (int jd = 0; jd < 16; jd++)
                mma16816(o[jd], a2, bv[jd]);
        }
    }

    // ---- epilogue: ctx hi-only fp16 into g_a1 [S, DMODEL] ----
    const float invA = 1.0f / lA;
    const float invB = 1.0f / lB;
    const int rA = qt * 64 + wid * 16 + g;
    const int rB = rA + 8;
#pragma unroll
    for (int jd = 0; jd < 16; jd++) {
        const int c = 8 * jd + 2 * tig;
        const size_t col = (size_t)h * HDIM + c;
        __half2 ha = __floats2half2_rn(o[jd][0] * invA, o[jd][1] * invA);
        __half2 hb = __floats2half2_rn(o[jd][2] * invB, o[jd][3] * invB);
        *(__half2*)(g_a1 + (size_t)rA * DMODEL + col) = ha;
        *(__half2*)(g_a1 + (size_t)rB * DMODEL + col) = hb;
    }
}

// ---------------------------------------------------------------------------
extern "C" void kernel_launch(void* const* d_in, const int* in_sizes, int n_in,
                              void* d_out, int out_size)
{
    const float* x     = (const float*)d_in[0];
    const float* cosp  = (const float*)d_in[1];
    const float* sinp  = (const float*)d_in[2];
    const float* w_qkv = (const float*)d_in[3];
    const float* b_qkv = (const float*)d_in[4];
    const float* wq    = (const float*)d_in[5];
    const float* wk    = (const float*)d_in[6];
    const float* w_out = (const float*)d_in[7];
    const float* b_out = (const float*)d_in[8];
    float* out = (float*)d_out;

    float* qkv_p;
    __half *a1_p, *w1_p, *w2_p;
    cudaGetSymbolAddress((void**)&qkv_p, g_qkv);
    cudaGetSymbolAddress((void**)&a1_p,  g_a1);
    cudaGetSymbolAddress((void**)&w1_p,  g_w1);
    cudaGetSymbolAddress((void**)&w2_p,  g_w2);

    const int GEMM_SMEM = 3 * 32768;
    cudaFuncSetAttribute(gemm_mma, cudaFuncAttributeMaxDynamicSharedMemorySize, GEMM_SMEM);
    cudaFuncSetAttribute(flash_tc, cudaFuncAttributeMaxDynamicSharedMemorySize, 81920);

    // conversions (hi-only everywhere)
    conv_wt_hi<<<dim3(NQKV / 32, DMODEL / 32), 128>>>(w_qkv, w1_p, DMODEL, NQKV);
    conv_wt_hi<<<dim3(DMODEL / 32, DMODEL / 32), 128>>>(w_out, w2_p, DMODEL, DMODEL);
    conv_act_hi<<<(SEQ * DMODEL / 8 + 255) / 256, 256>>>(x, a1_p, SEQ * DMODEL / 8);

    // QKV projection: K=5120
    gemm_mma<<<dim3(SEQ / 128, NQKV / 128), 256, GEMM_SMEM>>>(
        a1_p, w1_p, b_qkv, qkv_p, NQKV, DMODEL);

    // RMSNorm + RoPE; V transpose
    norm_rope<<<SEQ, 256>>>(cosp, sinp, wq, wk);
    conv_vt<<<dim3(SEQ / 32, DMODEL / 32), 256>>>();

    // tensor-core attention (writes ctx hi into g_a1)
    flash_tc<<<dim3(SEQ / 64, NHEAD), 128, 81920>>>();

    // output projection: K=5120
    gemm_mma<<<dim3(SEQ / 128, DMODEL / 128), 256, GEMM_SMEM>>>(
        a1_p, w2_p, b_out, out, DMODEL, DMODEL);
}